// round 7
// baseline (speedup 1.0000x reference)
#include <cuda_runtime.h>
#include <cuda_fp16.h>

#define DIMF 1536
#define SEQ  1560
#define LKV  4680
#define NH   12
#define HD   128

// scratch (allocation-free: device globals)
__device__ float g_q[SEQ * DIMF];
__device__ float g_k[SEQ * DIMF];
__device__ float g_v[SEQ * DIMF];
__device__ float g_o[SEQ * DIMF];

__device__ __forceinline__ unsigned h2u(__half2 h) {
    return *reinterpret_cast<unsigned*>(&h);
}
__device__ __forceinline__ unsigned pk2(float a, float b) {
    return h2u(__floats2half2_rn(a, b));
}

// D += A*B  (m16n8k16 fp16 inputs, fp32 accum, row.col)
__device__ __forceinline__ void mma16(float* d, const unsigned* a, const unsigned* b) {
    asm volatile(
        "mma.sync.aligned.m16n8k16.row.col.f32.f16.f16.f32 "
        "{%0,%1,%2,%3},{%4,%5,%6,%7},{%8,%9},{%0,%1,%2,%3};"
        : "+f"(d[0]), "+f"(d[1]), "+f"(d[2]), "+f"(d[3])
        : "r"(a[0]), "r"(a[1]), "r"(a[2]), "r"(a[3]), "r"(b[0]), "r"(b[1]));
}

__device__ __forceinline__ void ldm4(unsigned& r0, unsigned& r1, unsigned& r2, unsigned& r3,
                                     const void* p) {
    unsigned a = (unsigned)__cvta_generic_to_shared(p);
    asm volatile("ldmatrix.sync.aligned.m8n8.x4.shared.b16 {%0,%1,%2,%3},[%4];"
                 : "=r"(r0), "=r"(r1), "=r"(r2), "=r"(r3) : "r"(a));
}
__device__ __forceinline__ void ldm4t(unsigned& r0, unsigned& r1, unsigned& r2, unsigned& r3,
                                      const void* p) {
    unsigned a = (unsigned)__cvta_generic_to_shared(p);
    asm volatile("ldmatrix.sync.aligned.m8n8.x4.trans.shared.b16 {%0,%1,%2,%3},[%4];"
                 : "=r"(r0), "=r"(r1), "=r"(r2), "=r"(r3) : "r"(a));
}

__device__ __forceinline__ uint4 cvt8(float4 a, float4 b) {
    uint4 u;
    u.x = pk2(a.x, a.y); u.y = pk2(a.z, a.w);
    u.z = pk2(b.x, b.y); u.w = pk2(b.z, b.w);
    return u;
}

// ---------------------------------------------------------------------------
// GEMM: out[M,1536] = A[M,1536] @ W[1536,1536] + bias. fp16 mma m16n8k16.
// BM=BN=128, BK=32, 256 threads (8 warps 2x4), warp tile 64x32.
// As[128][40] halfs (row-major [m][k]); Bs[32][136] halfs ([k][n]).
// ---------------------------------------------------------------------------
#define GASTR 40
#define GBSTR 136
__global__ __launch_bounds__(256) void gemm_f16(
    const float* __restrict__ A, const float* __restrict__ W,
    const float* __restrict__ bias, float* __restrict__ out, int M)
{
    __shared__ __half As[128 * GASTR];
    __shared__ __half Bs[32 * GBSTR];
    const int bm = blockIdx.x * 128, bn = blockIdx.y * 128;
    const int tid = threadIdx.x, lane = tid & 31, warp = tid >> 5;
    const int wm = (warp >> 2) * 64, wn = (warp & 3) * 32;
    const int gi = lane >> 2, ti = lane & 3;

    float acc[4][4][4];
#pragma unroll
    for (int i = 0; i < 4; i++)
#pragma unroll
        for (int j = 0; j < 4; j++)
#pragma unroll
            for (int c = 0; c < 4; c++) acc[i][j][c] = 0.f;

    // staging indices
    const int ar = tid >> 1, ac = (tid & 1) * 16;   // A: row 0..127, col grp
    const int br = tid >> 3, bc = (tid & 7) * 16;   // B: row 0..31,  col grp

    float4 ra[4], rb[4];
    {
        const float* ap = A + (size_t)(bm + ar) * DIMF + ac;
        bool ok = bm + ar < M;
#pragma unroll
        for (int u = 0; u < 4; u++)
            ra[u] = ok ? *(const float4*)(ap + 4 * u) : make_float4(0, 0, 0, 0);
        const float* bp = W + (size_t)br * DIMF + bn + bc;
#pragma unroll
        for (int u = 0; u < 4; u++) rb[u] = *(const float4*)(bp + 4 * u);
    }

    for (int k0 = 0; k0 < DIMF; k0 += 32) {
        *(uint4*)&As[ar * GASTR + ac]     = cvt8(ra[0], ra[1]);
        *(uint4*)&As[ar * GASTR + ac + 8] = cvt8(ra[2], ra[3]);
        *(uint4*)&Bs[br * GBSTR + bc]     = cvt8(rb[0], rb[1]);
        *(uint4*)&Bs[br * GBSTR + bc + 8] = cvt8(rb[2], rb[3]);
        __syncthreads();

        if (k0 + 32 < DIMF) {
            const float* ap = A + (size_t)(bm + ar) * DIMF + k0 + 32 + ac;
            bool ok = bm + ar < M;
#pragma unroll
            for (int u = 0; u < 4; u++)
                ra[u] = ok ? *(const float4*)(ap + 4 * u) : make_float4(0, 0, 0, 0);
            const float* bp = W + (size_t)(k0 + 32 + br) * DIMF + bn + bc;
#pragma unroll
            for (int u = 0; u < 4; u++) rb[u] = *(const float4*)(bp + 4 * u);
        }

#pragma unroll
        for (int ks = 0; ks < 2; ks++) {
            const int kk = ks * 16;
            unsigned a[4][4], b[2][4];
#pragma unroll
            for (int mt = 0; mt < 4; mt++)
                ldm4(a[mt][0], a[mt][1], a[mt][2], a[mt][3],
                     &As[(wm + 16 * mt + (lane & 15)) * GASTR + kk + 8 * (lane >> 4)]);
#pragma unroll
            for (int ntp = 0; ntp < 2; ntp++)
                ldm4t(b[ntp][0], b[ntp][1], b[ntp][2], b[ntp][3],
                      &Bs[(kk + (lane & 7) + 8 * ((lane >> 3) & 1)) * GBSTR
                          + wn + 16 * ntp + 8 * (lane >> 4)]);
#pragma unroll
            for (int mt = 0; mt < 4; mt++)
#pragma unroll
                for (int ntp = 0; ntp < 2; ntp++) {
                    mma16(acc[mt][2 * ntp],     a[mt], &b[ntp][0]);
                    mma16(acc[mt][2 * ntp + 1], a[mt], &b[ntp][2]);
                }
        }
        __syncthreads();
    }

    // epilogue + bias
#pragma unroll
    for (int mt = 0; mt < 4; mt++) {
#pragma unroll
        for (int nt = 0; nt < 4; nt++) {
            int gr0 = bm + wm + 16 * mt + gi;
            int col = bn + wn + 8 * nt + 2 * ti;
            float2 bv = *(const float2*)&bias[col];
            if (gr0 < M) {
                float2 r = { acc[mt][nt][0] + bv.x, acc[mt][nt][1] + bv.y };
                *(float2*)(out + (size_t)gr0 * DIMF + col) = r;
            }
            if (gr0 + 8 < M) {
                float2 r = { acc[mt][nt][2] + bv.x, acc[mt][nt][3] + bv.y };
                *(float2*)(out + (size_t)(gr0 + 8) * DIMF + col) = r;
            }
        }
    }
}

// ---------------------------------------------------------------------------
// RMSNorm + RoPE (unchanged, 11us)
// ---------------------------------------------------------------------------
__global__ __launch_bounds__(256) void rmsrope(
    float* __restrict__ qbuf, float* __restrict__ kbuf,
    const float* __restrict__ gq, const float* __restrict__ gk,
    const float* __restrict__ fre, const float* __restrict__ fim)
{
    const int t = blockIdx.x;
    float* row = (blockIdx.y == 0 ? qbuf : kbuf) + (size_t)t * DIMF;
    const float* g = blockIdx.y == 0 ? gq : gk;
    const int tid = threadIdx.x;

    float ss = 0.f;
#pragma unroll
    for (int u = 0; u < 6; u++) { float v = row[tid + u * 256]; ss += v * v; }
#pragma unroll
    for (int off = 16; off; off >>= 1) ss += __shfl_xor_sync(0xffffffffu, ss, off);
    __shared__ float red[8];
    if ((tid & 31) == 0) red[tid >> 5] = ss;
    __syncthreads();
    float tot = red[0] + red[1] + red[2] + red[3] + red[4] + red[5] + red[6] + red[7];
    float r = rsqrtf(tot * (1.f / 1536.f) + 1e-6f);

    const int wi = t % 52;
    const int hi = t / 52;
#pragma unroll
    for (int u = 0; u < 3; u++) {
        int p = tid + u * 256;
        int hh = p >> 6, c = p & 63;
        int d0 = hh * 128 + 2 * c;
        int frow = (c < 22) ? 3 : (c < 43) ? hi : wi;
        float cr = fre[frow * 64 + c], ci = fim[frow * 64 + c];
        float v0 = row[d0] * r * g[d0];
        float v1 = row[d0 + 1] * r * g[d0 + 1];
        row[d0]     = v0 * cr - v1 * ci;
        row[d0 + 1] = v0 * ci + v1 * cr;
    }
}

// ---------------------------------------------------------------------------
// Flash attention, fp16 mma m16n8k16. Block = (64 q, head), 128 threads,
// 4 warps x 16 rows. Q frags in regs; K,V staged row-major [kv][d] as half
// (stride 136). QK B-frags: ldmatrix; PV B-frags: ldmatrix.trans (free
// transpose); P stays in registers (S-frag layout == A-frag layout).
// smem: 2 * 64*136*2 = 34816 B -> 2+ blocks/SM.
// ---------------------------------------------------------------------------
#define KVSTR 136
__global__ __launch_bounds__(128, 2) void attn_f16(
    const float* __restrict__ q, const float* __restrict__ knew,
    const float* __restrict__ vnew, const float* __restrict__ ck,
    const float* __restrict__ cv, float* __restrict__ out)
{
    extern __shared__ __half sm[];
    __half* Ks = sm;                 // [kv 64][d 136]
    __half* Vs = sm + 64 * KVSTR;    // [kv 64][d 136]

    const int h = blockIdx.y, q0 = blockIdx.x * 64;
    const int tid = threadIdx.x, lane = tid & 31, warp = tid >> 5;
    const int gi = lane >> 2, ti = lane & 3;

    // Q fragments: warp rows q0+16w+gi / +8; 8 k16-tiles x 4 half2 regs
    unsigned qf[8][4];
    {
        const float sc = 0.08838834764831845f; // 1/sqrt(128)
        int r0 = q0 + warp * 16 + gi, r1 = r0 + 8;
        const float* p0 = q + (size_t)r0 * DIMF + h * HD;
        const float* p1 = q + (size_t)r1 * DIMF + h * HD;
        bool k0ok = r0 < SEQ, k1ok = r1 < SEQ;
#pragma unroll
        for (int kt = 0; kt < 8; kt++) {
            int c = 16 * kt + 2 * ti;
            float2 u0 = k0ok ? *(const float2*)(p0 + c)     : make_float2(0, 0);
            float2 u2 = k0ok ? *(const float2*)(p0 + c + 8) : make_float2(0, 0);
            float2 u1 = k1ok ? *(const float2*)(p1 + c)     : make_float2(0, 0);
            float2 u3 = k1ok ? *(const float2*)(p1 + c + 8) : make_float2(0, 0);
            qf[kt][0] = pk2(u0.x * sc, u0.y * sc);
            qf[kt][1] = pk2(u1.x * sc, u1.y * sc);
            qf[kt][2] = pk2(u2.x * sc, u2.y * sc);
            qf[kt][3] = pk2(u3.x * sc, u3.y * sc);
        }
    }

    float m0v = -1e30f, m1v = -1e30f, l0 = 0.f, l1 = 0.f;
    float o[16][4];
#pragma unroll
    for (int i = 0; i < 16; i++)
#pragma unroll
        for (int c = 0; c < 4; c++) o[i][c] = 0.f;

    // staging: 2 threads per kv row, 64 d each
    const int sr = tid >> 1, sd = (tid & 1) * 64;

    for (int kv0 = 0; kv0 < LKV; kv0 += 64) {
        {
            int j = kv0 + sr;
            bool ok = j < LKV;
            const float* ksrc; const float* vsrc;
            if (j < 1560)      { ksrc = ck + ((size_t)j * NH + h) * HD;
                                 vsrc = cv + ((size_t)j * NH + h) * HD; }
            else if (j < 3120) { ksrc = ck + ((size_t)(j + 1560) * NH + h) * HD;
                                 vsrc = cv + ((size_t)(j + 1560) * NH + h) * HD; }
            else               { ksrc = knew + (size_t)(j - 3120) * DIMF + h * HD;
                                 vsrc = vnew + (size_t)(j - 3120) * DIMF + h * HD; }
#pragma unroll
            for (int u = 0; u < 8; u++) {
                int d = sd + u * 8;
                float4 a = ok ? *(const float4*)(ksrc + d)     : make_float4(0, 0, 0, 0);
                float4 b = ok ? *(const float4*)(ksrc + d + 4) : make_float4(0, 0, 0, 0);
                *(uint4*)&Ks[sr * KVSTR + d] = cvt8(a, b);
                float4 c = ok ? *(const float4*)(vsrc + d)     : make_float4(0, 0, 0, 0);
                float4 e = ok ? *(const float4*)(vsrc + d + 4) : make_float4(0, 0, 0, 0);
                *(uint4*)&Vs[sr * KVSTR + d] = cvt8(c, e);
            }
        }
        __syncthreads();

        // --- S = Q K^T : warp computes 16 x 64 ---
        float s[8][4];
#pragma unroll
        for (int nt = 0; nt < 8; nt++)
#pragma unroll
            for (int c = 0; c < 4; c++) s[nt][c] = 0.f;
#pragma unroll
        for (int kt = 0; kt < 8; kt++) {
            const int kk = 16 * kt;
#pragma unroll
            for (int ntp = 0; ntp < 4; ntp++) {
                unsigned b[4];
                ldm4(b[0], b[1], b[2], b[3],
                     &Ks[(16 * ntp + (lane & 7) + 8 * ((lane >> 4) & 1)) * KVSTR
                         + kk + 8 * ((lane >> 3) & 1)]);
                mma16(s[2 * ntp],     qf[kt], &b[0]);
                mma16(s[2 * ntp + 1], qf[kt], &b[2]);
            }
        }

        // tail mask
        if (kv0 + 64 > LKV) {
#pragma unroll
            for (int nt = 0; nt < 8; nt++) {
                int col = kv0 + 8 * nt + 2 * ti;
                if (col >= LKV)     { s[nt][0] = -1e30f; s[nt][2] = -1e30f; }
                if (col + 1 >= LKV) { s[nt][1] = -1e30f; s[nt][3] = -1e30f; }
            }
        }

        // --- online softmax; produce P fragments in registers ---
        unsigned pf[4][4];
        {
            float mx = -1e30f;
#pragma unroll
            for (int nt = 0; nt < 8; nt++) mx = fmaxf(mx, fmaxf(s[nt][0], s[nt][1]));
            mx = fmaxf(mx, __shfl_xor_sync(0xffffffffu, mx, 1));
            mx = fmaxf(mx, __shfl_xor_sync(0xffffffffu, mx, 2));
            float mn = fmaxf(m0v, mx);
            float al = __expf(m0v - mn);
            float rs = 0.f;
#pragma unroll
            for (int nt = 0; nt < 8; nt++) {
                float p0 = __expf(s[nt][0] - mn), p1 = __expf(s[nt][1] - mn);
                rs += p0 + p1;
                s[nt][0] = p0; s[nt][1] = p1;
            }
            rs += __shfl_xor_sync(0xffffffffu, rs, 1);
            rs += __shfl_xor_sync(0xffffffffu, rs, 2);
            l0 = l0 * al + rs; m0v = mn;
#pragma unroll
            for (int nt = 0; nt < 16; nt++) { o[nt][0] *= al; o[nt][1] *= al; }
        }
        {
            float mx = -1e30f;
#pragma unroll
            for (int nt = 0; nt < 8; nt++) mx = fmaxf(mx, fmaxf(s[nt][2], s[nt][3]));
            mx = fmaxf(mx, __shfl_xor_sync(0xffffffffu, mx, 1));
            mx = fmaxf(mx, __shfl_xor_sync(0xffffffffu, mx, 2));
            float mn = fmaxf(m1v, mx);
            float al = __expf(m1v - mn);
            float rs = 0.f;
#pragma unroll
            for (int nt = 0; nt < 8; nt++) {
                float p2 = __expf(s[nt][2] - mn), p3 = __expf(s[nt][3] - mn);
                rs += p2 + p3;
                s[nt][2] = p2; s[nt][3] = p3;
            }
            rs += __shfl_xor_sync(0xffffffffu, rs, 1);
            rs += __shfl_xor_sync(0xffffffffu, rs, 2);
            l1 = l1 * al + rs; m1v = mn;
#pragma unroll
            for (int nt = 0; nt < 16; nt++) { o[nt][2] *= al; o[nt][3] *= al; }
        }
        // S-frag -> A-frag: pf[j] covers kv 16j..16j+15
#pragma unroll
        for (int j = 0; j < 4; j++) {
            pf[j][0] = pk2(s[2 * j][0],     s[2 * j][1]);
            pf[j][1] = pk2(s[2 * j][2],     s[2 * j][3]);
            pf[j][2] = pk2(s[2 * j + 1][0], s[2 * j + 1][1]);
            pf[j][3] = pk2(s[2 * j + 1][2], s[2 * j + 1][3]);
        }

        // --- O += P V ---
#pragma unroll
        for (int j = 0; j < 4; j++) {
#pragma unroll
            for (int ntp = 0; ntp < 8; ntp++) {
                unsigned b[4];
                ldm4t(b[0], b[1], b[2], b[3],
                      &Vs[(16 * j + (lane & 7) + 8 * ((lane >> 3) & 1)) * KVSTR
                          + 16 * ntp + 8 * ((lane >> 4) & 1)]);
                mma16(o[2 * ntp],     pf[j], &b[0]);
                mma16(o[2 * ntp + 1], pf[j], &b[2]);
            }
        }
        __syncthreads();
    }

    // epilogue
    {
        int r0 = q0 + warp * 16 + gi, r1 = r0 + 8;
        float i0 = 1.f / l0, i1 = 1.f / l1;
#pragma unroll
        for (int nt = 0; nt < 16; nt++) {
            int c = h * HD + 8 * nt + 2 * ti;
            if (r0 < SEQ) {
                float2 v = { o[nt][0] * i0, o[nt][1] * i0 };
                *(float2*)(out + (size_t)r0 * DIMF + c) = v;
            }
            if (r1 < SEQ) {
                float2 v = { o[nt][2] * i1, o[nt][3] * i1 };
                *(float2*)(out + (size_t)r1 * DIMF + c) = v;
            }
        }
    }
}

// ---------------------------------------------------------------------------
extern "C" void kernel_launch(void* const* d_in, const int* in_sizes, int n_in,
                              void* d_out, int out_size)
{
    (void)in_sizes; (void)n_in; (void)out_size;
    const float* x   = (const float*)d_in[0];
    const float* ck  = (const float*)d_in[1];
    const float* cv  = (const float*)d_in[2];
    const float* fre = (const float*)d_in[3];
    const float* fim = (const float*)d_in[4];
    const float* wq  = (const float*)d_in[5];
    const float* bq  = (const float*)d_in[6];
    const float* wk  = (const float*)d_in[7];
    const float* bk  = (const float*)d_in[8];
    const float* wv  = (const float*)d_in[9];
    const float* bv  = (const float*)d_in[10];
    const float* wo  = (const float*)d_in[11];
    const float* bo  = (const float*)d_in[12];
    const float* gq  = (const float*)d_in[13];
    const float* gk  = (const float*)d_in[14];
    float* out = (float*)d_out;

    float *q, *k, *v, *o;
    cudaGetSymbolAddress((void**)&q, g_q);
    cudaGetSymbolAddress((void**)&k, g_k);
    cudaGetSymbolAddress((void**)&v, g_v);
    cudaGetSymbolAddress((void**)&o, g_o);

    const int attn_smem = 2 * 64 * KVSTR * (int)sizeof(__half); // 34816
    cudaFuncSetAttribute(attn_f16, cudaFuncAttributeMaxDynamicSharedMemorySize, attn_smem);

    dim3 gg(13, 12);
    gemm_f16<<<gg, 256>>>(x, wq, bq, q, SEQ);
    gemm_f16<<<gg, 256>>>(x, wk, bk, k, SEQ);
    gemm_f16<<<gg, 256>>>(x, wv, bv, v, SEQ);
    rmsrope<<<dim3(SEQ, 2), 256>>>(q, k, gq, gk, fre, fim);
    attn_f16<<<dim3(25, NH), 128, attn_smem>>>(q, k, v, ck, cv, o);
    gemm_f16<<<gg, 256>>>(o, wo, bo, out, SEQ);
}

// round 8
// speedup vs baseline: 1.2980x; 1.2980x over previous
#include <cuda_runtime.h>
#include <cuda_fp16.h>

#define DIMF 1536
#define SEQ  1560
#define LKV  4680
#define NH   12
#define HD   128

// ---------------- device-global scratch (allocation-free) ----------------
__device__ float  g_q[SEQ * DIMF];          // fp32 q pre-norm
__device__ float  g_k[SEQ * DIMF];          // fp32 k pre-norm
__device__ float  g_v[SEQ * DIMF];          // fp32 v
__device__ __half g_xh[SEQ * DIMF];         // fp16 x
__device__ __half g_whq[DIMF * DIMF];       // fp16 weights
__device__ __half g_whk[DIMF * DIMF];
__device__ __half g_whv[DIMF * DIMF];
__device__ __half g_who[DIMF * DIMF];
__device__ __half g_qh[NH * SEQ * HD];      // fp16 q, per-head, RoPE'd, pre-scaled
__device__ __half g_kh[NH * LKV * HD];      // fp16 logical K, per-head contiguous
__device__ __half g_vh[NH * LKV * HD];      // fp16 logical V
__device__ __half g_oh[SEQ * DIMF];         // fp16 attention output

__device__ __forceinline__ unsigned pk2(float a, float b) {
    __half2 h = __floats2half2_rn(a, b);
    return *reinterpret_cast<unsigned*>(&h);
}
__device__ __forceinline__ uint4 cvt8(float4 a, float4 b) {
    uint4 u;
    u.x = pk2(a.x, a.y); u.y = pk2(a.z, a.w);
    u.z = pk2(b.x, b.y); u.w = pk2(b.z, b.w);
    return u;
}

// D += A*B  (m16n8k16 fp16 inputs, fp32 accum, row.col)
__device__ __forceinline__ void mma16(float* d, const unsigned* a, const unsigned* b) {
    asm volatile(
        "mma.sync.aligned.m16n8k16.row.col.f32.f16.f16.f32 "
        "{%0,%1,%2,%3},{%4,%5,%6,%7},{%8,%9},{%0,%1,%2,%3};"
        : "+f"(d[0]), "+f"(d[1]), "+f"(d[2]), "+f"(d[3])
        : "r"(a[0]), "r"(a[1]), "r"(a[2]), "r"(a[3]), "r"(b[0]), "r"(b[1]));
}
__device__ __forceinline__ void ldm4(unsigned& r0, unsigned& r1, unsigned& r2, unsigned& r3,
                                     const void* p) {
    unsigned a = (unsigned)__cvta_generic_to_shared(p);
    asm volatile("ldmatrix.sync.aligned.m8n8.x4.shared.b16 {%0,%1,%2,%3},[%4];"
                 : "=r"(r0), "=r"(r1), "=r"(r2), "=r"(r3) : "r"(a));
}
__device__ __forceinline__ void ldm4t(unsigned& r0, unsigned& r1, unsigned& r2, unsigned& r3,
                                      const void* p) {
    unsigned a = (unsigned)__cvta_generic_to_shared(p);
    asm volatile("ldmatrix.sync.aligned.m8n8.x4.trans.shared.b16 {%0,%1,%2,%3},[%4];"
                 : "=r"(r0), "=r"(r1), "=r"(r2), "=r"(r3) : "r"(a));
}
__device__ __forceinline__ void cpa16(void* dst, const void* src) {
    unsigned d = (unsigned)__cvta_generic_to_shared(dst);
    asm volatile("cp.async.cg.shared.global [%0], [%1], 16;" :: "r"(d), "l"(src));
}

// ---------------------------------------------------------------------------
// fp32 -> fp16 bulk convert (n % 8 == 0)
// ---------------------------------------------------------------------------
__global__ void f2h(const float* __restrict__ in, __half* __restrict__ out, int n) {
    int i = (blockIdx.x * blockDim.x + threadIdx.x) * 8;
    if (i < n) {
        float4 a = *(const float4*)(in + i);
        float4 b = *(const float4*)(in + i + 4);
        *(uint4*)(out + i) = cvt8(a, b);
    }
}

// ---------------------------------------------------------------------------
// cache rows -> per-head contiguous fp16 logical KV (j in [0,3120))
// ---------------------------------------------------------------------------
__global__ void cacheconv(const float* __restrict__ ck, const float* __restrict__ cv,
                          __half* __restrict__ kh, __half* __restrict__ vh) {
    int j = blockIdx.x;               // logical 0..3119
    int h = blockIdx.y;
    int jj = j < 1560 ? j : j + 1560; // physical cache row
    int d = threadIdx.x * 2;          // 64 threads
    float2 a = *(const float2*)(ck + ((size_t)jj * NH + h) * HD + d);
    float2 b = *(const float2*)(cv + ((size_t)jj * NH + h) * HD + d);
    *(__half2*)(kh + ((size_t)h * LKV + j) * HD + d) = __floats2half2_rn(a.x, a.y);
    *(__half2*)(vh + ((size_t)h * LKV + j) * HD + d) = __floats2half2_rn(b.x, b.y);
}

// ---------------------------------------------------------------------------
// v fp32 [t][1536] -> vh[h][3120+t][128] fp16
// ---------------------------------------------------------------------------
__global__ void vconv(const float* __restrict__ v, __half* __restrict__ vh) {
    int t = blockIdx.x;
    int e0 = threadIdx.x * 2;         // 256 threads
#pragma unroll
    for (int u = 0; u < 3; u++) {
        int e = e0 + u * 512;
        int hh = e >> 7, d = e & 127;
        float2 a = *(const float2*)(v + (size_t)t * DIMF + e);
        *(__half2*)(vh + ((size_t)hh * LKV + 3120 + t) * HD + d) = __floats2half2_rn(a.x, a.y);
    }
}

// ---------------------------------------------------------------------------
// RMSNorm + RoPE; writes fp16 per-head outputs. q is pre-scaled by 1/sqrt(128).
// ---------------------------------------------------------------------------
__global__ __launch_bounds__(256) void rmsrope(
    const float* __restrict__ qbuf, const float* __restrict__ kbuf,
    const float* __restrict__ gq, const float* __restrict__ gk,
    const float* __restrict__ fre, const float* __restrict__ fim,
    __half* __restrict__ qh, __half* __restrict__ kh)
{
    const int t = blockIdx.x;
    const bool isq = blockIdx.y == 0;
    const float* row = (isq ? qbuf : kbuf) + (size_t)t * DIMF;
    const float* g = isq ? gq : gk;
    const int tid = threadIdx.x;

    float ss = 0.f;
#pragma unroll
    for (int u = 0; u < 6; u++) { float v = row[tid + u * 256]; ss += v * v; }
#pragma unroll
    for (int off = 16; off; off >>= 1) ss += __shfl_xor_sync(0xffffffffu, ss, off);
    __shared__ float red[8];
    if ((tid & 31) == 0) red[tid >> 5] = ss;
    __syncthreads();
    float tot = red[0] + red[1] + red[2] + red[3] + red[4] + red[5] + red[6] + red[7];
    float r = rsqrtf(tot * (1.f / 1536.f) + 1e-6f);
    const float sc = isq ? 0.08838834764831845f : 1.0f;

    const int wi = t % 52;
    const int hi = t / 52;
#pragma unroll
    for (int u = 0; u < 3; u++) {
        int p = tid + u * 256;
        int hh = p >> 6, c = p & 63;
        int d0 = hh * 128 + 2 * c;
        int frow = (c < 22) ? 3 : (c < 43) ? hi : wi;
        float cr = fre[frow * 64 + c], ci = fim[frow * 64 + c];
        float v0 = row[d0] * r * g[d0];
        float v1 = row[d0 + 1] * r * g[d0 + 1];
        float y0 = (v0 * cr - v1 * ci) * sc;
        float y1 = (v0 * ci + v1 * cr) * sc;
        __half* dst = isq ? qh + ((size_t)hh * SEQ + t) * HD + 2 * c
                          : kh + ((size_t)hh * LKV + 3120 + t) * HD + 2 * c;
        *(__half2*)dst = __floats2half2_rn(y0, y1);
    }
}

// ---------------------------------------------------------------------------
// GEMM: out[M,1536] = A[M,1536] @ W[1536,1536] + bias. fp16 in, fp32 out.
// BM=BN=128, BK=32, 256 threads, warp tile 64x32, register prefetch.
// ---------------------------------------------------------------------------
#define GASTR 40
#define GBSTR 136
__global__ __launch_bounds__(256) void gemm_h(
    const __half* __restrict__ A, const __half* __restrict__ W,
    const float* __restrict__ bias, float* __restrict__ out, int M)
{
    __shared__ __half As[128 * GASTR];
    __shared__ __half Bs[32 * GBSTR];
    const int bm = blockIdx.x * 128, bn = blockIdx.y * 128;
    const int tid = threadIdx.x, lane = tid & 31, warp = tid >> 5;
    const int wm = (warp >> 2) * 64, wn = (warp & 3) * 32;
    const int gi = lane >> 2, ti = lane & 3;

    float acc[4][4][4];
#pragma unroll
    for (int i = 0; i < 4; i++)
#pragma unroll
        for (int j = 0; j < 4; j++)
#pragma unroll
            for (int c = 0; c < 4; c++) acc[i][j][c] = 0.f;

    const int ar = tid >> 1, ac = (tid & 1) * 16;   // A: 2 thr/row, 16 halfs each
    const int br = tid >> 3, bc = (tid & 7) * 16;   // B: 8 thr/row

    const uint4 z4 = {0, 0, 0, 0};
    uint4 ra[2], rb[2];
    {
        bool ok = bm + ar < M;
        const __half* ap = A + (size_t)(bm + ar) * DIMF + ac;
        ra[0] = ok ? *(const uint4*)ap : z4;
        ra[1] = ok ? *(const uint4*)(ap + 8) : z4;
        const __half* bp = W + (size_t)br * DIMF + bn + bc;
        rb[0] = *(const uint4*)bp;
        rb[1] = *(const uint4*)(bp + 8);
    }

    for (int k0 = 0; k0 < DIMF; k0 += 32) {
        *(uint4*)&As[ar * GASTR + ac]     = ra[0];
        *(uint4*)&As[ar * GASTR + ac + 8] = ra[1];
        *(uint4*)&Bs[br * GBSTR + bc]     = rb[0];
        *(uint4*)&Bs[br * GBSTR + bc + 8] = rb[1];
        __syncthreads();

        if (k0 + 32 < DIMF) {
            bool ok = bm + ar < M;
            const __half* ap = A + (size_t)(bm + ar) * DIMF + k0 + 32 + ac;
            ra[0] = ok ? *(const uint4*)ap : z4;
            ra[1] = ok ? *(const uint4*)(ap + 8) : z4;
            const __half* bp = W + (size_t)(k0 + 32 + br) * DIMF + bn + bc;
            rb[0] = *(const uint4*)bp;
            rb[1] = *(const uint4*)(bp + 8);
        }

#pragma unroll
        for (int ks = 0; ks < 2; ks++) {
            const int kk = ks * 16;
            unsigned a[4][4], b[2][4];
#pragma unroll
            for (int mt = 0; mt < 4; mt++)
                ldm4(a[mt][0], a[mt][1], a[mt][2], a[mt][3],
                     &As[(wm + 16 * mt + (lane & 15)) * GASTR + kk + 8 * (lane >> 4)]);
#pragma unroll
            for (int ntp = 0; ntp < 2; ntp++)
                ldm4t(b[ntp][0], b[ntp][1], b[ntp][2], b[ntp][3],
                      &Bs[(kk + (lane & 7) + 8 * ((lane >> 3) & 1)) * GBSTR
                          + wn + 16 * ntp + 8 * (lane >> 4)]);
#pragma unroll
            for (int mt = 0; mt < 4; mt++)
#pragma unroll
                for (int ntp = 0; ntp < 2; ntp++) {
                    mma16(acc[mt][2 * ntp],     a[mt], &b[ntp][0]);
                    mma16(acc[mt][2 * ntp + 1], a[mt], &b[ntp][2]);
                }
        }
        __syncthreads();
    }

#pragma unroll
    for (int mt = 0; mt < 4; mt++) {
#pragma unroll
        for (int nt = 0; nt < 4; nt++) {
            int gr0 = bm + wm + 16 * mt + gi;
            int col = bn + wn + 8 * nt + 2 * ti;
            float2 bv = *(const float2*)&bias[col];
            if (gr0 < M) {
                float2 r = { acc[mt][nt][0] + bv.x, acc[mt][nt][1] + bv.y };
                *(float2*)(out + (size_t)gr0 * DIMF + col) = r;
            }
            if (gr0 + 8 < M) {
                float2 r = { acc[mt][nt][2] + bv.x, acc[mt][nt][3] + bv.y };
                *(float2*)(out + (size_t)(gr0 + 8) * DIMF + col) = r;
            }
        }
    }
}

// ---------------------------------------------------------------------------
// Flash attention, fp16, q-tile 128, 8 warps. KV fp16 per-head contiguous;
// cp.async double-buffered staging. P in registers. Output fp16 to g_oh.
// smem: 2 bufs * (K+V) * 64*136 halfs = 69632 B.
// ---------------------------------------------------------------------------
#define KVS 136
#define TILEB (64 * KVS)   // halfs per K (or V) tile buffer
__global__ __launch_bounds__(256, 1) void attn_h(
    const __half* __restrict__ qh, const __half* __restrict__ kh,
    const __half* __restrict__ vh, __half* __restrict__ oh)
{
    extern __shared__ __half sm[];
    __half* Ks = sm;               // [2][64][KVS]
    __half* Vs = sm + 2 * TILEB;   // [2][64][KVS]

    const int h = blockIdx.y, q0 = blockIdx.x * 128;
    const int tid = threadIdx.x, lane = tid & 31, warp = tid >> 5;
    const int gi = lane >> 2, ti = lane & 3;

    const __half* kbase = kh + (size_t)h * LKV * HD;
    const __half* vbase = vh + (size_t)h * LKV * HD;

    // staging map: thread -> (row, 64B column group), 4x 16B cp.async per array
    const int srow = tid >> 2, scol = (tid & 3) * 32;   // col offset in halfs

    // Q fragments (fp16, pre-scaled): warp rows q0+16w+gi / +8
    unsigned qf[8][4];
    {
        int r0 = q0 + warp * 16 + gi, r1 = r0 + 8;
        const __half* p0 = qh + ((size_t)h * SEQ + r0) * HD;
        const __half* p1 = qh + ((size_t)h * SEQ + r1) * HD;
        bool ok0 = r0 < SEQ, ok1 = r1 < SEQ;
#pragma unroll
        for (int kt = 0; kt < 8; kt++) {
            int c = 16 * kt + 2 * ti;
            qf[kt][0] = ok0 ? *(const unsigned*)(p0 + c)     : 0u;
            qf[kt][2] = ok0 ? *(const unsigned*)(p0 + c + 8) : 0u;
            qf[kt][1] = ok1 ? *(const unsigned*)(p1 + c)     : 0u;
            qf[kt][3] = ok1 ? *(const unsigned*)(p1 + c + 8) : 0u;
        }
    }

    float m0v = -1e30f, m1v = -1e30f, l0 = 0.f, l1 = 0.f;
    float o[16][4];
#pragma unroll
    for (int i = 0; i < 16; i++)
#pragma unroll
        for (int c = 0; c < 4; c++) o[i][c] = 0.f;

    const int NT = (LKV + 63) / 64;   // 74

    // prologue: stage tile 0 into buffer 0
    {
        int j = srow; // kv0 = 0
        const __half* kp = kbase + (size_t)j * HD + scol;
        const __half* vp = vbase + (size_t)j * HD + scol;
        __half* kd = Ks + srow * KVS + scol;
        __half* vd = Vs + srow * KVS + scol;
#pragma unroll
        for (int u = 0; u < 4; u++) {
            cpa16(kd + u * 8, kp + u * 8);
            cpa16(vd + u * 8, vp + u * 8);
        }
        asm volatile("cp.async.commit_group;");
    }

    for (int t = 0; t < NT; t++) {
        const int buf = t & 1;
        if (t + 1 < NT) {
            int j = (t + 1) * 64 + srow;
            if (j > LKV - 1) j = LKV - 1;   // masked later
            const int nb = (t + 1) & 1;
            const __half* kp = kbase + (size_t)j * HD + scol;
            const __half* vp = vbase + (size_t)j * HD + scol;
            __half* kd = Ks + nb * TILEB + srow * KVS + scol;
            __half* vd = Vs + nb * TILEB + srow * KVS + scol;
#pragma unroll
            for (int u = 0; u < 4; u++) {
                cpa16(kd + u * 8, kp + u * 8);
                cpa16(vd + u * 8, vp + u * 8);
            }
            asm volatile("cp.async.commit_group;");
            asm volatile("cp.async.wait_group 1;");
        } else {
            asm volatile("cp.async.wait_group 0;");
        }
        __syncthreads();

        const __half* Kb = Ks + buf * TILEB;
        const __half* Vb = Vs + buf * TILEB;
        const int kv0 = t * 64;

        // --- S = Q K^T : warp computes 16 x 64 ---
        float s[8][4];
#pragma unroll
        for (int nt = 0; nt < 8; nt++)
#pragma unroll
            for (int c = 0; c < 4; c++) s[nt][c] = 0.f;
#pragma unroll
        for (int kt = 0; kt < 8; kt++) {
            const int kk = 16 * kt;
#pragma unroll
            for (int ntp = 0; ntp < 4; ntp++) {
                unsigned b[4];
                ldm4(b[0], b[1], b[2], b[3],
                     &Kb[(16 * ntp + (lane & 7) + 8 * ((lane >> 4) & 1)) * KVS
                         + kk + 8 * ((lane >> 3) & 1)]);
                mma16(s[2 * ntp],     qf[kt], &b[0]);
                mma16(s[2 * ntp + 1], qf[kt], &b[2]);
            }
        }

        // tail mask
        if (kv0 + 64 > LKV) {
#pragma unroll
            for (int nt = 0; nt < 8; nt++) {
                int col = kv0 + 8 * nt + 2 * ti;
                if (col >= LKV)     { s[nt][0] = -1e30f; s[nt][2] = -1e30f; }
                if (col + 1 >= LKV) { s[nt][1] = -1e30f; s[nt][3] = -1e30f; }
            }
        }

        // --- online softmax; P frags in registers ---
        unsigned pf[4][4];
        {
            float mx = -1e30f;
#pragma unroll
            for (int nt = 0; nt < 8; nt++) mx = fmaxf(mx, fmaxf(s[nt][0], s[nt][1]));
            mx = fmaxf(mx, __shfl_xor_sync(0xffffffffu, mx, 1));
            mx = fmaxf(mx, __shfl_xor_sync(0xffffffffu, mx, 2));
            float mn = fmaxf(m0v, mx);
            float al = __expf(m0v - mn);
            float rs = 0.f;
#pragma unroll
            for (int nt = 0; nt < 8; nt++) {
                float p0 = __expf(s[nt][0] - mn), p1 = __expf(s[nt][1] - mn);
                rs += p0 + p1;
                s[nt][0] = p0; s[nt][1] = p1;
            }
            rs += __shfl_xor_sync(0xffffffffu, rs, 1);
            rs += __shfl_xor_sync(0xffffffffu, rs, 2);
            l0 = l0 * al + rs; m0v = mn;
#pragma unroll
            for (int nt = 0; nt < 16; nt++) { o[nt][0] *= al; o[nt][1] *= al; }
        }
        {
            float mx = -1e30f;
#pragma unroll
            for (int nt = 0; nt < 8; nt++) mx = fmaxf(mx, fmaxf(s[nt][2], s[nt][3]));
            mx = fmaxf(mx, __shfl_xor_sync(0xffffffffu, mx, 1));
            mx = fmaxf(mx, __shfl_xor_sync(0xffffffffu, mx, 2));
            float mn = fmaxf(m1v, mx);
            float al = __expf(m1v - mn);
            float rs = 0.f;
#pragma unroll
            for (int nt = 0; nt < 8; nt++) {
                float p2 = __expf(s[nt][2] - mn), p3 = __expf(s[nt][3] - mn);
                rs += p2 + p3;
                s[nt][2] = p2; s[nt][3] = p3;
            }
            rs += __shfl_xor_sync(0xffffffffu, rs, 1);
            rs += __shfl_xor_sync(0xffffffffu, rs, 2);
            l1 = l1 * al + rs; m1v = mn;
#pragma unroll
            for (int nt = 0; nt < 16; nt++) { o[nt][2] *= al; o[nt][3] *= al; }
        }
#pragma unroll
        for (int j = 0; j < 4; j++) {
            pf[j][0] = pk2(s[2 * j][0],     s[2 * j][1]);
            pf[j][1] = pk2(s[2 * j][2],     s[2 * j][3]);
            pf[j][2] = pk2(s[2 * j + 1][0], s[2 * j + 1][1]);
            pf[j][3] = pk2(s[2 * j + 1][2], s[2 * j + 1][3]);
        }

        // --- O += P V ---
#pragma unroll
        for (int j = 0; j < 4; j++) {
#pragma unroll
            for (int ntp = 0; ntp < 8; ntp++) {
                unsigned b[4];
                ldm4t(b[0], b[1], b[2], b[3],
                      &Vb[(16 * j + (lane & 7) + 8 * ((lane >> 3) & 1)) * KVS
                          + 16 * ntp + 8 * ((lane >> 4) & 1)]);
                mma16(o[2 * ntp],     pf[j], &b[0]);
                mma16(o[2 * ntp + 1], pf[j], &b[2]);
            }
        }
        __syncthreads();   // all reads of buf done before it is re-staged
    }

    // epilogue: fp16 output
    {
        int r0 = q0 + warp * 16 + gi, r1 = r0 + 8;
        float i0 = 1.f / l0, i1 = 1.f / l1;
#pragma unroll
        for (int nt = 0; nt < 16; nt++) {
            int c = h * HD + 8 * nt + 2 * ti;
            if (r0 < SEQ)
                *(__half2*)(oh + (size_t)r0 * DIMF + c) =
                    __floats2half2_rn(o[nt][0] * i0, o[nt][1] * i0);
            if (r1 < SEQ)
                *(__half2*)(oh + (size_t)r1 * DIMF + c) =
                    __floats2half2_rn(o[nt][2] * i1, o[nt][3] * i1);
        }
    }
}

// ---------------------------------------------------------------------------
extern "C" void kernel_launch(void* const* d_in, const int* in_sizes, int n_in,
                              void* d_out, int out_size)
{
    (void)in_sizes; (void)n_in; (void)out_size;
    const float* x   = (const float*)d_in[0];
    const float* ck  = (const float*)d_in[1];
    const float* cv  = (const float*)d_in[2];
    const float* fre = (const float*)d_in[3];
    const float* fim = (const float*)d_in[4];
    const float* wq  = (const float*)d_in[5];
    const float* bq  = (const float*)d_in[6];
    const float* wk  = (const float*)d_in[7];
    const float* bk  = (const float*)d_in[8];
    const float* wv  = (const float*)d_in[9];
    const float* bv  = (const float*)d_in[10];
    const float* wo  = (const float*)d_in[11];
    const float* bo  = (const float*)d_in[12];
    const float* gq  = (const float*)d_in[13];
    const float* gk  = (const float*)d_in[14];
    float* out = (float*)d_out;

    float *q, *k, *v;
    __half *xh, *whq, *whk, *whv, *who, *qh, *kh, *vh, *oh;
    cudaGetSymbolAddress((void**)&q, g_q);
    cudaGetSymbolAddress((void**)&k, g_k);
    cudaGetSymbolAddress((void**)&v, g_v);
    cudaGetSymbolAddress((void**)&xh, g_xh);
    cudaGetSymbolAddress((void**)&whq, g_whq);
    cudaGetSymbolAddress((void**)&whk, g_whk);
    cudaGetSymbolAddress((void**)&whv, g_whv);
    cudaGetSymbolAddress((void**)&who, g_who);
    cudaGetSymbolAddress((void**)&qh, g_qh);
    cudaGetSymbolAddress((void**)&kh, g_kh);
    cudaGetSymbolAddress((void**)&vh, g_vh);
    cudaGetSymbolAddress((void**)&oh, g_oh);

    const int attn_smem = 4 * TILEB * (int)sizeof(__half);  // 69632
    cudaFuncSetAttribute(attn_h, cudaFuncAttributeMaxDynamicSharedMemorySize, attn_smem);

    const int NW = DIMF * DIMF;        // 2359296
    const int NX = SEQ * DIMF;         // 2396160
    f2h<<<(NX / 8 + 255) / 256, 256>>>(x, xh, NX);
    f2h<<<(NW / 8 + 255) / 256, 256>>>(wq, whq, NW);
    f2h<<<(NW / 8 + 255) / 256, 256>>>(wk, whk, NW);
    f2h<<<(NW / 8 + 255) / 256, 256>>>(wv, whv, NW);
    f2h<<<(NW / 8 + 255) / 256, 256>>>(wo, who, NW);
    cacheconv<<<dim3(3120, NH), 64>>>(ck, cv, kh, vh);

    dim3 gg(13, 12);
    gemm_h<<<gg, 256>>>(xh, whq, bq, q, SEQ);
    gemm_h<<<gg, 256>>>(xh, whk, bk, k, SEQ);
    gemm_h<<<gg, 256>>>(xh, whv, bv, v, SEQ);
    rmsrope<<<dim3(SEQ, 2), 256>>>(q, k, gq, gk, fre, fim, qh, kh);
    vconv<<<SEQ, 256>>>(v, vh);
    attn_h<<<dim3(13, NH), 256, attn_smem>>>(qh, kh, vh, oh);
    gemm_h<<<gg, 256>>>(oh, who, bo, out, SEQ);
}

// round 9
// speedup vs baseline: 1.4633x; 1.1273x over previous
#include <cuda_runtime.h>
#include <cuda_fp16.h>

#define DIMF 1536
#define SEQ  1560
#define LKV  4680
#define NH   12
#define HD   128

// ---------------- device-global scratch (allocation-free) ----------------
__device__ float  g_q[SEQ * DIMF];          // fp32 q pre-norm
__device__ float  g_k[SEQ * DIMF];          // fp32 k pre-norm
__device__ __half g_xh[SEQ * DIMF];         // fp16 x
__device__ __half g_wqkv[DIMF * 3 * DIMF];  // fp16 fused [k][4608] qkv weights
__device__ __half g_who[DIMF * DIMF];       // fp16 wo
__device__ __half g_qh[NH * SEQ * HD];      // fp16 q, per-head, RoPE'd, pre-scaled (incl log2e)
__device__ __half g_kh[NH * LKV * HD];      // fp16 logical K, per-head contiguous
__device__ __half g_vh[NH * LKV * HD];      // fp16 logical V
__device__ __half g_oh[SEQ * DIMF];         // fp16 attention output

__device__ __forceinline__ unsigned pk2(float a, float b) {
    __half2 h = __floats2half2_rn(a, b);
    return *reinterpret_cast<unsigned*>(&h);
}
__device__ __forceinline__ uint4 cvt8(float4 a, float4 b) {
    uint4 u;
    u.x = pk2(a.x, a.y); u.y = pk2(a.z, a.w);
    u.z = pk2(b.x, b.y); u.w = pk2(b.z, b.w);
    return u;
}
__device__ __forceinline__ void mma16(float* d, const unsigned* a, const unsigned* b) {
    asm volatile(
        "mma.sync.aligned.m16n8k16.row.col.f32.f16.f16.f32 "
        "{%0,%1,%2,%3},{%4,%5,%6,%7},{%8,%9},{%0,%1,%2,%3};"
        : "+f"(d[0]), "+f"(d[1]), "+f"(d[2]), "+f"(d[3])
        : "r"(a[0]), "r"(a[1]), "r"(a[2]), "r"(a[3]), "r"(b[0]), "r"(b[1]));
}
__device__ __forceinline__ void ldm4(unsigned* r, const void* p) {
    unsigned a = (unsigned)__cvta_generic_to_shared(p);
    asm volatile("ldmatrix.sync.aligned.m8n8.x4.shared.b16 {%0,%1,%2,%3},[%4];"
                 : "=r"(r[0]), "=r"(r[1]), "=r"(r[2]), "=r"(r[3]) : "r"(a));
}
__device__ __forceinline__ void ldm4t(unsigned* r, const void* p) {
    unsigned a = (unsigned)__cvta_generic_to_shared(p);
    asm volatile("ldmatrix.sync.aligned.m8n8.x4.trans.shared.b16 {%0,%1,%2,%3},[%4];"
                 : "=r"(r[0]), "=r"(r[1]), "=r"(r[2]), "=r"(r[3]) : "r"(a));
}
__device__ __forceinline__ void cpa16(void* dst, const void* src) {
    unsigned d = (unsigned)__cvta_generic_to_shared(dst);
    asm volatile("cp.async.cg.shared.global [%0], [%1], 16;" :: "r"(d), "l"(src));
}

// ---------------------------------------------------------------------------
// fp32 -> fp16 bulk convert (n % 8 == 0)
// ---------------------------------------------------------------------------
__global__ void f2h(const float* __restrict__ in, __half* __restrict__ out, int n) {
    int i = (blockIdx.x * blockDim.x + threadIdx.x) * 8;
    if (i < n) {
        float4 a = *(const float4*)(in + i);
        float4 b = *(const float4*)(in + i + 4);
        *(uint4*)(out + i) = cvt8(a, b);
    }
}

// ---------------------------------------------------------------------------
// fuse wq|wk|wv -> fp16 [k][4608]
// ---------------------------------------------------------------------------
__global__ void wfuse(const float* __restrict__ wq, const float* __restrict__ wk,
                      const float* __restrict__ wv, __half* __restrict__ out) {
    int idx = blockIdx.x * 256 + threadIdx.x;   // one uint4 (8 halfs) each
    if (idx >= DIMF * 576) return;              // 4608/8 = 576
    int k = idx / 576, n = (idx - k * 576) * 8;
    int sel = n / DIMF, nn = n - sel * DIMF;
    const float* src = (sel == 0 ? wq : sel == 1 ? wk : wv) + (size_t)k * DIMF + nn;
    float4 a = *(const float4*)src;
    float4 b = *(const float4*)(src + 4);
    *(uint4*)(out + (size_t)k * 4608 + n) = cvt8(a, b);
}

// ---------------------------------------------------------------------------
// cache rows -> per-head contiguous fp16 logical KV (j in [0,3120))
// ---------------------------------------------------------------------------
__global__ void cacheconv(const float* __restrict__ ck, const float* __restrict__ cv,
                          __half* __restrict__ kh, __half* __restrict__ vh) {
    int j = blockIdx.x;
    int h = blockIdx.y;
    int jj = j < 1560 ? j : j + 1560;
    int d = threadIdx.x * 2;
    float2 a = *(const float2*)(ck + ((size_t)jj * NH + h) * HD + d);
    float2 b = *(const float2*)(cv + ((size_t)jj * NH + h) * HD + d);
    *(__half2*)(kh + ((size_t)h * LKV + j) * HD + d) = __floats2half2_rn(a.x, a.y);
    *(__half2*)(vh + ((size_t)h * LKV + j) * HD + d) = __floats2half2_rn(b.x, b.y);
}

// ---------------------------------------------------------------------------
// RMSNorm + RoPE; fp16 per-head outputs. q pre-scaled by log2e/sqrt(128).
// ---------------------------------------------------------------------------
__global__ __launch_bounds__(256) void rmsrope(
    const float* __restrict__ qbuf, const float* __restrict__ kbuf,
    const float* __restrict__ gq, const float* __restrict__ gk,
    const float* __restrict__ fre, const float* __restrict__ fim,
    __half* __restrict__ qh, __half* __restrict__ kh)
{
    const int t = blockIdx.x;
    const bool isq = blockIdx.y == 0;
    const float* row = (isq ? qbuf : kbuf) + (size_t)t * DIMF;
    const float* g = isq ? gq : gk;
    const int tid = threadIdx.x;

    float ss = 0.f;
#pragma unroll
    for (int u = 0; u < 6; u++) { float v = row[tid + u * 256]; ss += v * v; }
#pragma unroll
    for (int off = 16; off; off >>= 1) ss += __shfl_xor_sync(0xffffffffu, ss, off);
    __shared__ float red[8];
    if ((tid & 31) == 0) red[tid >> 5] = ss;
    __syncthreads();
    float tot = red[0] + red[1] + red[2] + red[3] + red[4] + red[5] + red[6] + red[7];
    float r = rsqrtf(tot * (1.f / 1536.f) + 1e-6f);
    // q: 1/sqrt(128) * log2(e)  (softmax done in base-2)
    const float sc = isq ? 0.08838834764831845f * 1.4426950408889634f : 1.0f;

    const int wi = t % 52;
    const int hi = t / 52;
#pragma unroll
    for (int u = 0; u < 3; u++) {
        int p = tid + u * 256;
        int hh = p >> 6, c = p & 63;
        int d0 = hh * 128 + 2 * c;
        int frow = (c < 22) ? 3 : (c < 43) ? hi : wi;
        float cr = fre[frow * 64 + c], ci = fim[frow * 64 + c];
        float v0 = row[d0] * r * g[d0];
        float v1 = row[d0 + 1] * r * g[d0 + 1];
        float y0 = (v0 * cr - v1 * ci) * sc;
        float y1 = (v0 * ci + v1 * cr) * sc;
        __half* dst = isq ? qh + ((size_t)hh * SEQ + t) * HD + 2 * c
                          : kh + ((size_t)hh * LKV + 3120 + t) * HD + 2 * c;
        *(__half2*)dst = __floats2half2_rn(y0, y1);
    }
}

// ---------------------------------------------------------------------------
// GEMM core: BM=128, BN=128, BK=32, 128 threads (4 warps, warp tile 64x64),
// 3-stage cp.async pipeline, one bar.sync per k-iter.
// MODE 0: O-proj  (W ld 1536, fp32 out + bias)
// MODE 1: fused QKV (W ld 4608; q/k fp32, v fp16 into per-head layout)
// ---------------------------------------------------------------------------
#define GAS 40
#define GBS 136
#define ASTG (128 * GAS)
#define BSTG (32 * GBS)
#define GSTG (ASTG + BSTG)
#define NKT  48

template <int MODE, int LDW>
__global__ __launch_bounds__(128) void gemm_core(
    const __half* __restrict__ A, const __half* __restrict__ W,
    const float* __restrict__ b0, const float* __restrict__ b1,
    const float* __restrict__ b2,
    float* __restrict__ o0, float* __restrict__ o1, __half* __restrict__ o2)
{
    extern __shared__ __half gsm[];
    const int bm = blockIdx.x * 128, bn = blockIdx.y * 128;
    const int tid = threadIdx.x, lane = tid & 31, warp = tid >> 5;
    const int wm = (warp >> 1) * 64, wn = (warp & 1) * 64;
    const int gi = lane >> 2, ti = lane & 3;

    float acc[4][8][4];
#pragma unroll
    for (int i = 0; i < 4; i++)
#pragma unroll
        for (int j = 0; j < 8; j++)
#pragma unroll
            for (int c = 0; c < 4; c++) acc[i][j][c] = 0.f;

    int arow = bm + tid; if (arow > SEQ - 1) arow = SEQ - 1;
    const __half* asrc = A + (size_t)arow * DIMF;
    const int brow = tid >> 2, bcol = (tid & 3) * 32;
    const __half* bsrc = W + (size_t)brow * LDW + bn + bcol;

#define GSTAGE(S, KT)                                                        \
    {                                                                        \
        __half* as_ = gsm + (S) * GSTG;                                      \
        __half* bs_ = as_ + ASTG;                                            \
        const __half* ap_ = asrc + (KT) * 32;                                \
        const __half* bp_ = bsrc + (size_t)(KT) * 32 * LDW;                  \
        _Pragma("unroll")                                                    \
        for (int u = 0; u < 4; u++) cpa16(as_ + tid * GAS + u * 8, ap_ + u * 8); \
        _Pragma("unroll")                                                    \
        for (int u = 0; u < 4; u++) cpa16(bs_ + brow * GBS + bcol + u * 8, bp_ + u * 8); \
        asm volatile("cp.async.commit_group;" ::: "memory");                 \
    }

    GSTAGE(0, 0)
    GSTAGE(1, 1)

    for (int kt = 0; kt < NKT; kt++) {
        if (kt < NKT - 1) asm volatile("cp.async.wait_group 1;" ::: "memory");
        else              asm volatile("cp.async.wait_group 0;" ::: "memory");
        __syncthreads();
        if (kt + 2 < NKT) { int s = (kt + 2) % 3; GSTAGE(s, kt + 2) }

        const __half* As = gsm + (kt % 3) * GSTG;
        const __half* Bs = As + ASTG;
#pragma unroll
        for (int ks = 0; ks < 2; ks++) {
            const int kk = ks * 16;
            unsigned a[4][4], b[4][4];
#pragma unroll
            for (int mt = 0; mt < 4; mt++)
                ldm4(a[mt], &As[(wm + 16 * mt + (lane & 15)) * GAS + kk + 8 * (lane >> 4)]);
#pragma unroll
            for (int ntp = 0; ntp < 4; ntp++)
                ldm4t(b[ntp], &Bs[(kk + (lane & 7) + 8 * ((lane >> 3) & 1)) * GBS
                                  + wn + 16 * ntp + 8 * (lane >> 4)]);
#pragma unroll
            for (int mt = 0; mt < 4; mt++)
#pragma unroll
                for (int ntp = 0; ntp < 4; ntp++) {
                    mma16(acc[mt][2 * ntp],     a[mt], &b[ntp][0]);
                    mma16(acc[mt][2 * ntp + 1], a[mt], &b[ntp][2]);
                }
        }
    }
#undef GSTAGE

    // ---- epilogue ----
    if (MODE == 0) {
#pragma unroll
        for (int mt = 0; mt < 4; mt++)
#pragma unroll
            for (int nt = 0; nt < 8; nt++) {
                int gr = bm + wm + 16 * mt + gi;
                int col = bn + wn + 8 * nt + 2 * ti;
                float2 bv = *(const float2*)&b0[col];
                if (gr < SEQ) {
                    float2 rr = { acc[mt][nt][0] + bv.x, acc[mt][nt][1] + bv.y };
                    *(float2*)(o0 + (size_t)gr * DIMF + col) = rr;
                }
                if (gr + 8 < SEQ) {
                    float2 rr = { acc[mt][nt][2] + bv.x, acc[mt][nt][3] + bv.y };
                    *(float2*)(o0 + (size_t)(gr + 8) * DIMF + col) = rr;
                }
            }
    } else {
        const int region = bn < DIMF ? 0 : bn < 2 * DIMF ? 1 : 2;
        const float* bp = region == 0 ? b0 + bn : region == 1 ? b1 + (bn - DIMF)
                                                              : b2 + (bn - 2 * DIMF);
#pragma unroll
        for (int mt = 0; mt < 4; mt++)
#pragma unroll
            for (int nt = 0; nt < 8; nt++) {
                int gr = bm + wm + 16 * mt + gi;
                int l = wn + 8 * nt + 2 * ti;
                float2 bv = *(const float2*)&bp[l];
                float v00 = acc[mt][nt][0] + bv.x, v01 = acc[mt][nt][1] + bv.y;
                float v10 = acc[mt][nt][2] + bv.x, v11 = acc[mt][nt][3] + bv.y;
                if (region == 0) {
                    int col = bn + l;
                    if (gr < SEQ)     *(float2*)(o0 + (size_t)gr * DIMF + col)       = make_float2(v00, v01);
                    if (gr + 8 < SEQ) *(float2*)(o0 + (size_t)(gr + 8) * DIMF + col) = make_float2(v10, v11);
                } else if (region == 1) {
                    int col = bn - DIMF + l;
                    if (gr < SEQ)     *(float2*)(o1 + (size_t)gr * DIMF + col)       = make_float2(v00, v01);
                    if (gr + 8 < SEQ) *(float2*)(o1 + (size_t)(gr + 8) * DIMF + col) = make_float2(v10, v11);
                } else {
                    int vcol = bn - 2 * DIMF + l;
                    int hh = vcol >> 7, d = vcol & 127;
                    if (gr < SEQ)
                        *(__half2*)(o2 + ((size_t)hh * LKV + 3120 + gr) * HD + d) =
                            __floats2half2_rn(v00, v01);
                    if (gr + 8 < SEQ)
                        *(__half2*)(o2 + ((size_t)hh * LKV + 3120 + gr + 8) * HD + d) =
                            __floats2half2_rn(v10, v11);
                }
            }
    }
}

// ---------------------------------------------------------------------------
// Flash attention, fp16, q-tile 64, 128 threads (4 warps), 3 blocks/SM.
// cp.async 2-stage KV staging; P in registers; softmax in base-2.
// smem: 2 bufs * (K+V) * 64*136 halfs = 69632 B.
// ---------------------------------------------------------------------------
#define KVS 136
#define TILEB (64 * KVS)
__global__ __launch_bounds__(128) void attn_h(
    const __half* __restrict__ qh, const __half* __restrict__ kh,
    const __half* __restrict__ vh, __half* __restrict__ oh)
{
    extern __shared__ __half sm[];
    __half* Ks = sm;               // [2][64][KVS]
    __half* Vs = sm + 2 * TILEB;   // [2][64][KVS]

    const int h = blockIdx.y, q0 = blockIdx.x * 64;
    const int tid = threadIdx.x, lane = tid & 31, warp = tid >> 5;
    const int gi = lane >> 2, ti = lane & 3;

    const __half* kbase = kh + (size_t)h * LKV * HD;
    const __half* vbase = vh + (size_t)h * LKV * HD;

    const int srow = tid >> 1, scol = (tid & 1) * 64;

    unsigned qf[8][4];
    {
        int r0 = q0 + warp * 16 + gi, r1 = r0 + 8;
        const __half* p0 = qh + ((size_t)h * SEQ + r0) * HD;
        const __half* p1 = qh + ((size_t)h * SEQ + r1) * HD;
        bool ok0 = r0 < SEQ, ok1 = r1 < SEQ;
#pragma unroll
        for (int kt = 0; kt < 8; kt++) {
            int c = 16 * kt + 2 * ti;
            qf[kt][0] = ok0 ? *(const unsigned*)(p0 + c)     : 0u;
            qf[kt][2] = ok0 ? *(const unsigned*)(p0 + c + 8) : 0u;
            qf[kt][1] = ok1 ? *(const unsigned*)(p1 + c)     : 0u;
            qf[kt][3] = ok1 ? *(const unsigned*)(p1 + c + 8) : 0u;
        }
    }

    float m0v = -1e30f, m1v = -1e30f, l0 = 0.f, l1 = 0.f;
    float o[16][4];
#pragma unroll
    for (int i = 0; i < 16; i++)
#pragma unroll
        for (int c = 0; c < 4; c++) o[i][c] = 0.f;

    const int NT = (LKV + 63) / 64;   // 74

    {   // prologue: tile 0 -> buf 0
        const __half* kp = kbase + (size_t)srow * HD + scol;
        const __half* vp = vbase + (size_t)srow * HD + scol;
        __half* kd = Ks + srow * KVS + scol;
        __half* vd = Vs + srow * KVS + scol;
#pragma unroll
        for (int u = 0; u < 8; u++) {
            cpa16(kd + u * 8, kp + u * 8);
            cpa16(vd + u * 8, vp + u * 8);
        }
        asm volatile("cp.async.commit_group;" ::: "memory");
    }

    for (int t = 0; t < NT; t++) {
        const int buf = t & 1;
        if (t + 1 < NT) {
            int j = (t + 1) * 64 + srow;
            if (j > LKV - 1) j = LKV - 1;
            const int nb = (t + 1) & 1;
            const __half* kp = kbase + (size_t)j * HD + scol;
            const __half* vp = vbase + (size_t)j * HD + scol;
            __half* kd = Ks + nb * TILEB + srow * KVS + scol;
            __half* vd = Vs + nb * TILEB + srow * KVS + scol;
#pragma unroll
            for (int u = 0; u < 8; u++) {
                cpa16(kd + u * 8, kp + u * 8);
                cpa16(vd + u * 8, vp + u * 8);
            }
            asm volatile("cp.async.commit_group;" ::: "memory");
            asm volatile("cp.async.wait_group 1;" ::: "memory");
        } else {
            asm volatile("cp.async.wait_group 0;" ::: "memory");
        }
        __syncthreads();

        const __half* Kb = Ks + buf * TILEB;
        const __half* Vb = Vs + buf * TILEB;
        const int kv0 = t * 64;

        // --- S = Q K^T (logits already in log2 domain via q pre-scale) ---
        float s[8][4];
#pragma unroll
        for (int nt = 0; nt < 8; nt++)
#pragma unroll
            for (int c = 0; c < 4; c++) s[nt][c] = 0.f;
#pragma unroll
        for (int kt = 0; kt < 8; kt++) {
            const int kk = 16 * kt;
#pragma unroll
            for (int ntp = 0; ntp < 4; ntp++) {
                unsigned b[4];
                ldm4(b, &Kb[(16 * ntp + (lane & 7) + 8 * ((lane >> 4) & 1)) * KVS
                            + kk + 8 * ((lane >> 3) & 1)]);
                mma16(s[2 * ntp],     qf[kt], &b[0]);
                mma16(s[2 * ntp + 1], qf[kt], &b[2]);
            }
        }

        if (kv0 + 64 > LKV) {
#pragma unroll
            for (int nt = 0; nt < 8; nt++) {
                int col = kv0 + 8 * nt + 2 * ti;
                if (col >= LKV)     { s[nt][0] = -1e30f; s[nt][2] = -1e30f; }
                if (col + 1 >= LKV) { s[nt][1] = -1e30f; s[nt][3] = -1e30f; }
            }
        }

        // --- online softmax (base-2) ---
        unsigned pf[4][4];
        {
            float mx = -1e30f;
#pragma unroll
            for (int nt = 0; nt < 8; nt++) mx = fmaxf(mx, fmaxf(s[nt][0], s[nt][1]));
            mx = fmaxf(mx, __shfl_xor_sync(0xffffffffu, mx, 1));
            mx = fmaxf(mx, __shfl_xor_sync(0xffffffffu, mx, 2));
            float mn = fmaxf(m0v, mx);
            float al = exp2f(m0v - mn);
            float rs = 0.f;
#pragma unroll
            for (int nt = 0; nt < 8; nt++) {
                float p0 = exp2f(s[nt][0] - mn), p1 = exp2f(s[nt][1] - mn);
                rs += p0 + p1;
                s[nt][0] = p0; s[nt][1] = p1;
            }
            rs += __shfl_xor_sync(0xffffffffu, rs, 1);
            rs += __shfl_xor_sync(0xffffffffu, rs, 2);
            l0 = l0 * al + rs; m0v = mn;
#pragma unroll
            for (int nt = 0; nt < 16; nt++) { o[nt][0] *= al; o[nt][1] *= al; }
        }
        {
            float mx = -1e30f;
#pragma unroll
            for (int nt = 0; nt < 8; nt++) mx = fmaxf(mx, fmaxf(s[nt][2], s[nt][3]));
            mx = fmaxf(mx, __shfl_xor_sync(0xffffffffu, mx, 1));
            mx = fmaxf(mx, __shfl_xor_sync(0xffffffffu, mx, 2));
            float mn = fmaxf(m1v, mx);
            float al = exp2f(m1v - mn);
            float rs = 0.f;
#pragma unroll
            for (int nt = 0; nt < 8; nt++) {
                float p2 = exp2f(s[nt][2] - mn), p3 = exp2f(s[nt][3] - mn);
                rs += p2 + p3;
                s[nt][2] = p2; s[nt][3] = p3;
            }
            rs += __shfl_xor_sync(0xffffffffu, rs, 1);
            rs += __shfl_xor_sync(0xffffffffu, rs, 2);
            l1 = l1 * al + rs; m1v = mn;
#pragma unroll
            for (int nt = 0; nt < 16; nt++) { o[nt][2] *= al; o[nt][3] *= al; }
        }
#pragma unroll
        for (int j = 0; j < 4; j++) {
            pf[j][0] = pk2(s[2 * j][0],     s[2 * j][1]);
            pf[j][1] = pk2(s[2 * j][2],     s[2 * j][3]);
            pf[j][2] = pk2(s[2 * j + 1][0], s[2 * j + 1][1]);
            pf[j][3] = pk2(s[2 * j + 1][2], s[2 * j + 1][3]);
        }

        // --- O += P V ---
#pragma unroll
        for (int j = 0; j < 4; j++) {
#pragma unroll
            for (int ntp = 0; ntp < 8; ntp++) {
                unsigned b[4];
                ldm4t(b, &Vb[(16 * j + (lane & 7) + 8 * ((lane >> 3) & 1)) * KVS
                             + 16 * ntp + 8 * ((lane >> 4) & 1)]);
                mma16(o[2 * ntp],     pf[j], &b[0]);
                mma16(o[2 * ntp + 1], pf[j], &b[2]);
            }
        }
        __syncthreads();
    }

    {
        int r0 = q0 + warp * 16 + gi, r1 = r0 + 8;
        float i0 = 1.f / l0, i1 = 1.f / l1;
#pragma unroll
        for (int nt = 0; nt < 16; nt++) {
            int c = h * HD + 8 * nt + 2 * ti;
            if (r0 < SEQ)
                *(__half2*)(oh + (size_t)r0 * DIMF + c) =
                    __floats2half2_rn(o[nt][0] * i0, o[nt][1] * i0);
            if (r1 < SEQ)
                *(__half2*)(oh + (size_t)r1 * DIMF + c) =
                    __floats2half2_rn(o[nt][2] * i1, o[nt][3] * i1);
        }
    }
}

// ---------------------------------------------------------------------------
extern "C" void kernel_launch(void* const* d_in, const int* in_sizes, int n_in,
                              void* d_out, int out_size)
{
    (void)in_sizes; (void)n_in; (void)out_size;
    const float* x   = (const float*)d_in[0];
    const float* ck  = (const float*)d_in[1];
    const float* cv  = (const float*)d_in[2];
    const float* fre = (const float*)d_in[3];
    const float* fim = (const float*)d_in[4];
    const float* wq  = (const float*)d_in[5];
    const float* bq  = (const float*)d_in[6];
    const float* wk  = (const float*)d_in[7];
    const float* bk  = (const float*)d_in[8];
    const float* wv  = (const float*)d_in[9];
    const float* bv  = (const float*)d_in[10];
    const float* wo  = (const float*)d_in[11];
    const float* bo  = (const float*)d_in[12];
    const float* gq  = (const float*)d_in[13];
    const float* gk  = (const float*)d_in[14];
    float* out = (float*)d_out;

    float *q, *k;
    __half *xh, *wqkv, *who, *qh, *kh, *vh, *oh;
    cudaGetSymbolAddress((void**)&q, g_q);
    cudaGetSymbolAddress((void**)&k, g_k);
    cudaGetSymbolAddress((void**)&xh, g_xh);
    cudaGetSymbolAddress((void**)&wqkv, g_wqkv);
    cudaGetSymbolAddress((void**)&who, g_who);
    cudaGetSymbolAddress((void**)&qh, g_qh);
    cudaGetSymbolAddress((void**)&kh, g_kh);
    cudaGetSymbolAddress((void**)&vh, g_vh);
    cudaGetSymbolAddress((void**)&oh, g_oh);

    const int gemm_smem = 3 * GSTG * (int)sizeof(__half);   // 56832
    const int attn_smem = 4 * TILEB * (int)sizeof(__half);  // 69632
    cudaFuncSetAttribute((const void*)gemm_core<1, 4608>,
                         cudaFuncAttributeMaxDynamicSharedMemorySize, gemm_smem);
    cudaFuncSetAttribute((const void*)gemm_core<0, 1536>,
                         cudaFuncAttributeMaxDynamicSharedMemorySize, gemm_smem);
    cudaFuncSetAttribute((const void*)attn_h,
                         cudaFuncAttributeMaxDynamicSharedMemorySize, attn_smem);

    const int NW = DIMF * DIMF;
    const int NX = SEQ * DIMF;
    f2h<<<(NX / 8 + 255) / 256, 256>>>(x, xh, NX);
    f2h<<<(NW / 8 + 255) / 256, 256>>>(wo, who, NW);
    wfuse<<<(DIMF * 576 + 255) / 256, 256>>>(wq, wk, wv, wqkv);
    cacheconv<<<dim3(3120, NH), 64>>>(ck, cv, kh, vh);

    // fused QKV GEMM: q,k fp32; v fp16 straight into per-head layout
    gemm_core<1, 4608><<<dim3(13, 36), 128, gemm_smem>>>(
        xh, wqkv, bq, bk, bv, q, k, vh);
    rmsrope<<<dim3(SEQ, 2), 256>>>(q, k, gq, gk, fre, fim, qh, kh);
    attn_h<<<dim3(25, NH), 128, attn_smem>>>(qh, kh, vh, oh);
    gemm_core<0, 1536><<<dim3(13, 12), 128, gemm_smem>>>(
        oh, who, bo, nullptr, nullptr, out, nullptr, nullptr);
}

// round 10
// speedup vs baseline: 1.4872x; 1.0163x over previous
#include <cuda_runtime.h>
#include <cuda_fp16.h>

#define DIMF 1536
#define SEQ  1560
#define LKV  4680
#define NH   12
#define HD   128

// ---------------- device-global scratch (allocation-free) ----------------
__device__ float  g_q[SEQ * DIMF];          // fp32 q pre-norm
__device__ float  g_k[SEQ * DIMF];          // fp32 k pre-norm
__device__ __half g_xh[SEQ * DIMF];         // fp16 x
__device__ __half g_wqkv[DIMF * 3 * DIMF];  // fp16 fused [k][4608] qkv weights
__device__ __half g_who[DIMF * DIMF];       // fp16 wo
__device__ __half g_qh[NH * SEQ * HD];      // fp16 q, per-head, RoPE'd, pre-scaled (incl log2e)
__device__ __half g_kh[NH * LKV * HD];      // fp16 logical K, per-head contiguous
__device__ __half g_vh[NH * LKV * HD];      // fp16 logical V
__device__ __half g_oh[SEQ * DIMF];         // fp16 attention output

__device__ __forceinline__ unsigned pk2(float a, float b) {
    __half2 h = __floats2half2_rn(a, b);
    return *reinterpret_cast<unsigned*>(&h);
}
__device__ __forceinline__ uint4 cvt8(float4 a, float4 b) {
    uint4 u;
    u.x = pk2(a.x, a.y); u.y = pk2(a.z, a.w);
    u.z = pk2(b.x, b.y); u.w = pk2(b.z, b.w);
    return u;
}
__device__ __forceinline__ void mma16(float* d, const unsigned* a, const unsigned* b) {
    asm volatile(
        "mma.sync.aligned.m16n8k16.row.col.f32.f16.f16.f32 "
        "{%0,%1,%2,%3},{%4,%5,%6,%7},{%8,%9},{%0,%1,%2,%3};"
        : "+f"(d[0]), "+f"(d[1]), "+f"(d[2]), "+f"(d[3])
        : "r"(a[0]), "r"(a[1]), "r"(a[2]), "r"(a[3]), "r"(b[0]), "r"(b[1]));
}
__device__ __forceinline__ void ldm4(unsigned* r, const void* p) {
    unsigned a = (unsigned)__cvta_generic_to_shared(p);
    asm volatile("ldmatrix.sync.aligned.m8n8.x4.shared.b16 {%0,%1,%2,%3},[%4];"
                 : "=r"(r[0]), "=r"(r[1]), "=r"(r[2]), "=r"(r[3]) : "r"(a));
}
__device__ __forceinline__ void ldm4t(unsigned* r, const void* p) {
    unsigned a = (unsigned)__cvta_generic_to_shared(p);
    asm volatile("ldmatrix.sync.aligned.m8n8.x4.trans.shared.b16 {%0,%1,%2,%3},[%4];"
                 : "=r"(r[0]), "=r"(r[1]), "=r"(r[2]), "=r"(r[3]) : "r"(a));
}
__device__ __forceinline__ void cpa16(void* dst, const void* src) {
    unsigned d = (unsigned)__cvta_generic_to_shared(dst);
    asm volatile("cp.async.cg.shared.global [%0], [%1], 16;" :: "r"(d), "l"(src));
}

// ---------------------------------------------------------------------------
// fp32 -> fp16 bulk convert (n % 8 == 0)
// ---------------------------------------------------------------------------
__global__ void f2h(const float* __restrict__ in, __half* __restrict__ out, int n) {
    int i = (blockIdx.x * blockDim.x + threadIdx.x) * 8;
    if (i < n) {
        float4 a = *(const float4*)(in + i);
        float4 b = *(const float4*)(in + i + 4);
        *(uint4*)(out + i) = cvt8(a, b);
    }
}

// ---------------------------------------------------------------------------
// fuse wq|wk|wv -> fp16 [k][4608]
// ---------------------------------------------------------------------------
__global__ void wfuse(const float* __restrict__ wq, const float* __restrict__ wk,
                      const float* __restrict__ wv, __half* __restrict__ out) {
    int idx = blockIdx.x * 256 + threadIdx.x;   // one uint4 (8 halfs) each
    if (idx >= DIMF * 576) return;              // 4608/8 = 576
    int k = idx / 576, n = (idx - k * 576) * 8;
    int sel = n / DIMF, nn = n - sel * DIMF;
    const float* src = (sel == 0 ? wq : sel == 1 ? wk : wv) + (size_t)k * DIMF + nn;
    float4 a = *(const float4*)src;
    float4 b = *(const float4*)(src + 4);
    *(uint4*)(out + (size_t)k * 4608 + n) = cvt8(a, b);
}

// ---------------------------------------------------------------------------
// cache rows -> per-head contiguous fp16 logical KV. Flat-indexed, 256 thr,
// one 8-half segment of both K and V per thread. 3120*12*16 = 599040 threads.
// ---------------------------------------------------------------------------
__global__ __launch_bounds__(256) void cacheconv(
    const float* __restrict__ ck, const float* __restrict__ cv,
    __half* __restrict__ kh, __half* __restrict__ vh)
{
    int idx = blockIdx.x * 256 + threadIdx.x;
    if (idx >= 3120 * NH * 16) return;
    int d8 = (idx & 15) * 8;            // 0..120 step 8
    int jh = idx >> 4;                  // (j, h)
    int h = jh % NH;
    int j = jh / NH;
    int jj = j < 1560 ? j : j + 1560;   // physical cache row
    size_t src = ((size_t)jj * NH + h) * HD + d8;
    size_t dst = ((size_t)h * LKV + j) * HD + d8;
    float4 a0 = *(const float4*)(ck + src);
    float4 a1 = *(const float4*)(ck + src + 4);
    *(uint4*)(kh + dst) = cvt8(a0, a1);
    float4 b0 = *(const float4*)(cv + src);
    float4 b1 = *(const float4*)(cv + src + 4);
    *(uint4*)(vh + dst) = cvt8(b0, b1);
}

// ---------------------------------------------------------------------------
// RMSNorm + RoPE; fp16 per-head outputs. q pre-scaled by log2e/sqrt(128).
// ---------------------------------------------------------------------------
__global__ __launch_bounds__(256) void rmsrope(
    const float* __restrict__ qbuf, const float* __restrict__ kbuf,
    const float* __restrict__ gq, const float* __restrict__ gk,
    const float* __restrict__ fre, const float* __restrict__ fim,
    __half* __restrict__ qh, __half* __restrict__ kh)
{
    const int t = blockIdx.x;
    const bool isq = blockIdx.y == 0;
    const float* row = (isq ? qbuf : kbuf) + (size_t)t * DIMF;
    const float* g = isq ? gq : gk;
    const int tid = threadIdx.x;

    float ss = 0.f;
#pragma unroll
    for (int u = 0; u < 6; u++) { float v = row[tid + u * 256]; ss += v * v; }
#pragma unroll
    for (int off = 16; off; off >>= 1) ss += __shfl_xor_sync(0xffffffffu, ss, off);
    __shared__ float red[8];
    if ((tid & 31) == 0) red[tid >> 5] = ss;
    __syncthreads();
    float tot = red[0] + red[1] + red[2] + red[3] + red[4] + red[5] + red[6] + red[7];
    float r = rsqrtf(tot * (1.f / 1536.f) + 1e-6f);
    const float sc = isq ? 0.08838834764831845f * 1.4426950408889634f : 1.0f;

    const int wi = t % 52;
    const int hi = t / 52;
#pragma unroll
    for (int u = 0; u < 3; u++) {
        int p = tid + u * 256;
        int hh = p >> 6, c = p & 63;
        int d0 = hh * 128 + 2 * c;
        int frow = (c < 22) ? 3 : (c < 43) ? hi : wi;
        float cr = fre[frow * 64 + c], ci = fim[frow * 64 + c];
        float v0 = row[d0] * r * g[d0];
        float v1 = row[d0 + 1] * r * g[d0 + 1];
        float y0 = (v0 * cr - v1 * ci) * sc;
        float y1 = (v0 * ci + v1 * cr) * sc;
        __half* dst = isq ? qh + ((size_t)hh * SEQ + t) * HD + 2 * c
                          : kh + ((size_t)hh * LKV + 3120 + t) * HD + 2 * c;
        *(__half2*)dst = __floats2half2_rn(y0, y1);
    }
}

// ---------------------------------------------------------------------------
// GEMM core: BM=128, BN=128, BK=32, 128 threads (4 warps, warp tile 64x64),
// 3-stage cp.async pipeline, one bar.sync per k-iter. 3 blocks/SM enforced.
// MODE 0: O-proj  (W ld 1536, fp32 out + bias)
// MODE 1: fused QKV (W ld 4608; q/k fp32, v fp16 into per-head layout)
// ---------------------------------------------------------------------------
#define GAS 40
#define GBS 136
#define ASTG (128 * GAS)
#define BSTG (32 * GBS)
#define GSTG (ASTG + BSTG)
#define NKT  48

template <int MODE, int LDW>
__global__ __launch_bounds__(128, 3) void gemm_core(
    const __half* __restrict__ A, const __half* __restrict__ W,
    const float* __restrict__ b0, const float* __restrict__ b1,
    const float* __restrict__ b2,
    float* __restrict__ o0, float* __restrict__ o1, __half* __restrict__ o2)
{
    extern __shared__ __half gsm[];
    const int bm = blockIdx.x * 128, bn = blockIdx.y * 128;
    const int tid = threadIdx.x, lane = tid & 31, warp = tid >> 5;
    const int wm = (warp >> 1) * 64, wn = (warp & 1) * 64;
    const int gi = lane >> 2, ti = lane & 3;

    float acc[4][8][4];
#pragma unroll
    for (int i = 0; i < 4; i++)
#pragma unroll
        for (int j = 0; j < 8; j++)
#pragma unroll
            for (int c = 0; c < 4; c++) acc[i][j][c] = 0.f;

    int arow = bm + tid; if (arow > SEQ - 1) arow = SEQ - 1;
    const __half* asrc = A + (size_t)arow * DIMF;
    const int brow = tid >> 2, bcol = (tid & 3) * 32;
    const __half* bsrc = W + (size_t)brow * LDW + bn + bcol;

#define GSTAGE(S, KT)                                                        \
    {                                                                        \
        __half* as_ = gsm + (S) * GSTG;                                      \
        __half* bs_ = as_ + ASTG;                                            \
        const __half* ap_ = asrc + (KT) * 32;                                \
        const __half* bp_ = bsrc + (size_t)(KT) * 32 * LDW;                  \
        _Pragma("unroll")                                                    \
        for (int u = 0; u < 4; u++) cpa16(as_ + tid * GAS + u * 8, ap_ + u * 8); \
        _Pragma("unroll")                                                    \
        for (int u = 0; u < 4; u++) cpa16(bs_ + brow * GBS + bcol + u * 8, bp_ + u * 8); \
        asm volatile("cp.async.commit_group;" ::: "memory");                 \
    }

    GSTAGE(0, 0)
    GSTAGE(1, 1)

    for (int kt = 0; kt < NKT; kt++) {
        if (kt < NKT - 1) asm volatile("cp.async.wait_group 1;" ::: "memory");
        else              asm volatile("cp.async.wait_group 0;" ::: "memory");
        __syncthreads();
        if (kt + 2 < NKT) { int s = (kt + 2) % 3; GSTAGE(s, kt + 2) }

        const __half* As = gsm + (kt % 3) * GSTG;
        const __half* Bs = As + ASTG;
#pragma unroll
        for (int ks = 0; ks < 2; ks++) {
            const int kk = ks * 16;
            unsigned a[4][4], b[4][4];
#pragma unroll
            for (int mt = 0; mt < 4; mt++)
                ldm4(a[mt], &As[(wm + 16 * mt + (lane & 15)) * GAS + kk + 8 * (lane >> 4)]);
#pragma unroll
            for (int ntp = 0; ntp < 4; ntp++)
                ldm4t(b[ntp], &Bs[(kk + (lane & 7) + 8 * ((lane >> 3) & 1)) * GBS
                                  + wn + 16 * ntp + 8 * (lane >> 4)]);
#pragma unroll
            for (int mt = 0; mt < 4; mt++)
#pragma unroll
                for (int ntp = 0; ntp < 4; ntp++) {
                    mma16(acc[mt][2 * ntp],     a[mt], &b[ntp][0]);
                    mma16(acc[mt][2 * ntp + 1], a[mt], &b[ntp][2]);
                }
        }
    }
#undef GSTAGE

    // ---- epilogue ----
    if (MODE == 0) {
#pragma unroll
        for (int mt = 0; mt < 4; mt++)
#pragma unroll
            for (int nt = 0; nt < 8; nt++) {
                int gr = bm + wm + 16 * mt + gi;
                int col = bn + wn + 8 * nt + 2 * ti;
                float2 bv = *(const float2*)&b0[col];
                if (gr < SEQ) {
                    float2 rr = { acc[mt][nt][0] + bv.x, acc[mt][nt][1] + bv.y };
                    *(float2*)(o0 + (size_t)gr * DIMF + col) = rr;
                }
                if (gr + 8 < SEQ) {
                    float2 rr = { acc[mt][nt][2] + bv.x, acc[mt][nt][3] + bv.y };
                    *(float2*)(o0 + (size_t)(gr + 8) * DIMF + col) = rr;
                }
            }
    } else {
        const int region = bn < DIMF ? 0 : bn < 2 * DIMF ? 1 : 2;
        const float* bp = region == 0 ? b0 + bn : region == 1 ? b1 + (bn - DIMF)
                                                              : b2 + (bn - 2 * DIMF);
#pragma unroll
        for (int mt = 0; mt < 4; mt++)
#pragma unroll
            for (int nt = 0; nt < 8; nt++) {
                int gr = bm + wm + 16 * mt + gi;
                int l = wn + 8 * nt + 2 * ti;
                float2 bv = *(const float2*)&bp[l];
                float v00 = acc[mt][nt][0] + bv.x, v01 = acc[mt][nt][1] + bv.y;
                float v10 = acc[mt][nt][2] + bv.x, v11 = acc[mt][nt][3] + bv.y;
                if (region == 0) {
                    int col = bn + l;
                    if (gr < SEQ)     *(float2*)(o0 + (size_t)gr * DIMF + col)       = make_float2(v00, v01);
                    if (gr + 8 < SEQ) *(float2*)(o0 + (size_t)(gr + 8) * DIMF + col) = make_float2(v10, v11);
                } else if (region == 1) {
                    int col = bn - DIMF + l;
                    if (gr < SEQ)     *(float2*)(o1 + (size_t)gr * DIMF + col)       = make_float2(v00, v01);
                    if (gr + 8 < SEQ) *(float2*)(o1 + (size_t)(gr + 8) * DIMF + col) = make_float2(v10, v11);
                } else {
                    int vcol = bn - 2 * DIMF + l;
                    int hh = vcol >> 7, d = vcol & 127;
                    if (gr < SEQ)
                        *(__half2*)(o2 + ((size_t)hh * LKV + 3120 + gr) * HD + d) =
                            __floats2half2_rn(v00, v01);
                    if (gr + 8 < SEQ)
                        *(__half2*)(o2 + ((size_t)hh * LKV + 3120 + gr + 8) * HD + d) =
                            __floats2half2_rn(v10, v11);
                }
            }
    }
}

// ---------------------------------------------------------------------------
// Flash attention, fp16, q-tile 64, 128 threads (4 warps), 3 blocks/SM
// enforced (single wave: 300 blocks <= 444 slots). cp.async 2-stage staging;
// P in registers; softmax base-2. smem: 2 bufs * (K+V) * 64*136 halfs.
// ---------------------------------------------------------------------------
#define KVS 136
#define TILEB (64 * KVS)
__global__ __launch_bounds__(128, 3) void attn_h(
    const __half* __restrict__ qh, const __half* __restrict__ kh,
    const __half* __restrict__ vh, __half* __restrict__ oh)
{
    extern __shared__ __half sm[];
    __half* Ks = sm;               // [2][64][KVS]
    __half* Vs = sm + 2 * TILEB;   // [2][64][KVS]

    const int h = blockIdx.y, q0 = blockIdx.x * 64;
    const int tid = threadIdx.x, lane = tid & 31, warp = tid >> 5;
    const int gi = lane >> 2, ti = lane & 3;

    const __half* kbase = kh + (size_t)h * LKV * HD;
    const __half* vbase = vh + (size_t)h * LKV * HD;

    const int srow = tid >> 1, scol = (tid & 1) * 64;

    unsigned qf[8][4];
    {
        int r0 = q0 + warp * 16 + gi, r1 = r0 + 8;
        const __half* p0 = qh + ((size_t)h * SEQ + r0) * HD;
        const __half* p1 = qh + ((size_t)h * SEQ + r1) * HD;
        bool ok0 = r0 < SEQ, ok1 = r1 < SEQ;
#pragma unroll
        for (int kt = 0; kt < 8; kt++) {
            int c = 16 * kt + 2 * ti;
            qf[kt][0] = ok0 ? *(const unsigned*)(p0 + c)     : 0u;
            qf[kt][2] = ok0 ? *(const unsigned*)(p0 + c + 8) : 0u;
            qf[kt][1] = ok1 ? *(const unsigned*)(p1 + c)     : 0u;
            qf[kt][3] = ok1 ? *(const unsigned*)(p1 + c + 8) : 0u;
        }
    }

    float m0v = -1e30f, m1v = -1e30f, l0 = 0.f, l1 = 0.f;
    float o[16][4];
#pragma unroll
    for (int i = 0; i < 16; i++)
#pragma unroll
        for (int c = 0; c < 4; c++) o[i][c] = 0.f;

    const int NT = (LKV + 63) / 64;   // 74

    {   // prologue: tile 0 -> buf 0
        const __half* kp = kbase + (size_t)srow * HD + scol;
        const __half* vp = vbase + (size_t)srow * HD + scol;
        __half* kd = Ks + srow * KVS + scol;
        __half* vd = Vs + srow * KVS + scol;
#pragma unroll
        for (int u = 0; u < 8; u++) {
            cpa16(kd + u * 8, kp + u * 8);
            cpa16(vd + u * 8, vp + u * 8);
        }
        asm volatile("cp.async.commit_group;" ::: "memory");
    }

    for (int t = 0; t < NT; t++) {
        const int buf = t & 1;
        if (t + 1 < NT) {
            int j = (t + 1) * 64 + srow;
            if (j > LKV - 1) j = LKV - 1;
            const int nb = (t + 1) & 1;
            const __half* kp = kbase + (size_t)j * HD + scol;
            const __half* vp = vbase + (size_t)j * HD + scol;
            __half* kd = Ks + nb * TILEB + srow * KVS + scol;
            __half* vd = Vs + nb * TILEB + srow * KVS + scol;
#pragma unroll
            for (int u = 0; u < 8; u++) {
                cpa16(kd + u * 8, kp + u * 8);
                cpa16(vd + u * 8, vp + u * 8);
            }
            asm volatile("cp.async.commit_group;" ::: "memory");
            asm volatile("cp.async.wait_group 1;" ::: "memory");
        } else {
            asm volatile("cp.async.wait_group 0;" ::: "memory");
        }
        __syncthreads();

        const __half* Kb = Ks + buf * TILEB;
        const __half* Vb = Vs + buf * TILEB;
        const int kv0 = t * 64;

        // --- S = Q K^T (logits in log2 domain via q pre-scale) ---
        float s[8][4];
#pragma unroll
        for (int nt = 0; nt < 8; nt++)
#pragma unroll
            for (int c = 0; c < 4; c++) s[nt][c] = 0.f;
#pragma unroll
        for (int kt = 0; kt < 8; kt++) {
            const int kk = 16 * kt;
#pragma unroll
            for (int ntp = 0; ntp < 4; ntp++) {
                unsigned b[4];
                ldm4(b, &Kb[(16 * ntp + (lane & 7) + 8 * ((lane >> 4) & 1)) * KVS
                            + kk + 8 * ((lane >> 3) & 1)]);
                mma16(s[2 * ntp],     qf[kt], &b[0]);
                mma16(s[2 * ntp + 1], qf[kt], &b[2]);
            }
        }

        if (kv0 + 64 > LKV) {
#pragma unroll
            for (int nt = 0; nt < 8; nt++) {
                int col = kv0 + 8 * nt + 2 * ti;
                if (col >= LKV)     { s[nt][0] = -1e30f; s[nt][2] = -1e30f; }
                if (col + 1 >= LKV) { s[nt][1] = -1e30f; s[nt][3] = -1e30f; }
            }
        }

        // --- online softmax (base-2) ---
        unsigned pf[4][4];
        {
            float mx = -1e30f;
#pragma unroll
            for (int nt = 0; nt < 8; nt++) mx = fmaxf(mx, fmaxf(s[nt][0], s[nt][1]));
            mx = fmaxf(mx, __shfl_xor_sync(0xffffffffu, mx, 1));
            mx = fmaxf(mx, __shfl_xor_sync(0xffffffffu, mx, 2));
            float mn = fmaxf(m0v, mx);
            float al = exp2f(m0v - mn);
            float rs = 0.f;
#pragma unroll
            for (int nt = 0; nt < 8; nt++) {
                float p0 = exp2f(s[nt][0] - mn), p1 = exp2f(s[nt][1] - mn);
                rs += p0 + p1;
                s[nt][0] = p0; s[nt][1] = p1;
            }
            rs += __shfl_xor_sync(0xffffffffu, rs, 1);
            rs += __shfl_xor_sync(0xffffffffu, rs, 2);
            l0 = l0 * al + rs; m0v = mn;
#pragma unroll
            for (int nt = 0; nt < 16; nt++) { o[nt][0] *= al; o[nt][1] *= al; }
        }
        {
            float mx = -1e30f;
#pragma unroll
            for (int nt = 0; nt < 8; nt++) mx = fmaxf(mx, fmaxf(s[nt][2], s[nt][3]));
            mx = fmaxf(mx, __shfl_xor_sync(0xffffffffu, mx, 1));
            mx = fmaxf(mx, __shfl_xor_sync(0xffffffffu, mx, 2));
            float mn = fmaxf(m1v, mx);
            float al = exp2f(m1v - mn);
            float rs = 0.f;
#pragma unroll
            for (int nt = 0; nt < 8; nt++) {
                float p2 = exp2f(s[nt][2] - mn), p3 = exp2f(s[nt][3] - mn);
                rs += p2 + p3;
                s[nt][2] = p2; s[nt][3] = p3;
            }
            rs += __shfl_xor_sync(0xffffffffu, rs, 1);
            rs += __shfl_xor_sync(0xffffffffu, rs, 2);
            l1 = l1 * al + rs; m1v = mn;
#pragma unroll
            for (int nt = 0; nt < 16; nt++) { o[nt][2] *= al; o[nt][3] *= al; }
        }
#pragma unroll
        for (int j = 0; j < 4; j++) {
            pf[j][0] = pk2(s[2 * j][0],     s[2 * j][1]);
            pf[j][1] = pk2(s[2 * j][2],     s[2 * j][3]);
            pf[j][2] = pk2(s[2 * j + 1][0], s[2 * j + 1][1]);
            pf[j][3] = pk2(s[2 * j + 1][2], s[2 * j + 1][3]);
        }

        // --- O += P V ---
#pragma unroll
        for (int j = 0; j < 4; j++) {
#pragma unroll
            for (int ntp = 0; ntp < 8; ntp++) {
                unsigned b[4];
                ldm4t(b, &Vb[(16 * j + (lane & 7) + 8 * ((lane >> 3) & 1)) * KVS
                             + 16 * ntp + 8 * ((lane >> 4) & 1)]);
                mma16(o[2 * ntp],     pf[j], &b[0]);
                mma16(o[2 * ntp + 1], pf[j], &b[2]);
            }
        }
        __syncthreads();
    }

    {
        int r0 = q0 + warp * 16 + gi, r1 = r0 + 8;
        float i0 = 1.f / l0, i1 = 1.f / l1;
#pragma unroll
        for (int nt = 0; nt < 16; nt++) {
            int c = h * HD + 8 * nt + 2 * ti;
            if (r0 < SEQ)
                *(__half2*)(oh + (size_t)r0 * DIMF + c) =
                    __floats2half2_rn(o[nt][0] * i0, o[nt][1] * i0);
            if (r1 < SEQ)
                *(__half2*)(oh + (size_t)r1 * DIMF + c) =
                    __floats2half2_rn(o[nt][2] * i1, o[nt][3] * i1);
        }
    }
}

// ---------------------------------------------------------------------------
extern "C" void kernel_launch(void* const* d_in, const int* in_sizes, int n_in,
                              void* d_out, int out_size)
{
    (void)in_sizes; (void)n_in; (void)out_size;
    const float* x   = (const float*)d_in[0];
    const float* ck  = (const float*)d_in[1];
    const float* cv  = (const float*)d_in[2];
    const float* fre = (const float*)d_in[3];
    const float* fim = (const float*)d_in[4];
    const float* wq  = (const float*)d_in[5];
    const float* bq  = (const float*)d_in[6];
    const float* wk  = (const float*)d_in[7];
    const float* bk  = (const float*)d_in[8];
    const float* wv  = (const float*)d_in[9];
    const float* bv  = (const float*)d_in[10];
    const float* wo  = (const float*)d_in[11];
    const float* bo  = (const float*)d_in[12];
    const float* gq  = (const float*)d_in[13];
    const float* gk  = (const float*)d_in[14];
    float* out = (float*)d_out;

    float *q, *k;
    __half *xh, *wqkv, *who, *qh, *kh, *vh, *oh;
    cudaGetSymbolAddress((void**)&q, g_q);
    cudaGetSymbolAddress((void**)&k, g_k);
    cudaGetSymbolAddress((void**)&xh, g_xh);
    cudaGetSymbolAddress((void**)&wqkv, g_wqkv);
    cudaGetSymbolAddress((void**)&who, g_who);
    cudaGetSymbolAddress((void**)&qh, g_qh);
    cudaGetSymbolAddress((void**)&kh, g_kh);
    cudaGetSymbolAddress((void**)&vh, g_vh);
    cudaGetSymbolAddress((void**)&oh, g_oh);

    const int gemm_smem = 3 * GSTG * (int)sizeof(__half);   // 56832
    const int attn_smem = 4 * TILEB * (int)sizeof(__half);  // 69632
    cudaFuncSetAttribute((const void*)gemm_core<1, 4608>,
                         cudaFuncAttributeMaxDynamicSharedMemorySize, gemm_smem);
    cudaFuncSetAttribute((const void*)gemm_core<0, 1536>,
                         cudaFuncAttributeMaxDynamicSharedMemorySize, gemm_smem);
    cudaFuncSetAttribute((const void*)attn_h,
                         cudaFuncAttributeMaxDynamicSharedMemorySize, attn_smem);

    const int NW = DIMF * DIMF;
    const int NX = SEQ * DIMF;
    f2h<<<(NX / 8 + 255) / 256, 256>>>(x, xh, NX);
    f2h<<<(NW / 8 + 255) / 256, 256>>>(wo, who, NW);
    wfuse<<<(DIMF * 576 + 255) / 256, 256>>>(wq, wk, wv, wqkv);
    cacheconv<<<(3120 * NH * 16 + 255) / 256, 256>>>(ck, cv, kh, vh);

    // fused QKV GEMM: q,k fp32; v fp16 straight into per-head layout
    gemm_core<1, 4608><<<dim3(13, 36), 128, gemm_smem>>>(
        xh, wqkv, bq, bk, bv, q, k, vh);
    rmsrope<<<dim3(SEQ, 2), 256>>>(q, k, gq, gk, fre, fim, qh, kh);
    attn_h<<<dim3(25, NH), 128, attn_smem>>>(qh, kh, vh, oh);
    gemm_core<0, 1536><<<dim3(13, 12), 128, gemm_smem>>>(
        oh, who, bo, nullptr, nullptr, out, nullptr, nullptr);
}

// round 11
// speedup vs baseline: 1.5140x; 1.0180x over previous
#include <cuda_runtime.h>
#include <cuda_fp16.h>

#define DIMF 1536
#define SEQ  1560
#define LKV  4680
#define NH   12
#define HD   128

// ---------------- device-global scratch (allocation-free) ----------------
__device__ float  g_q[SEQ * DIMF];          // fp32 q pre-norm
__device__ float  g_k[SEQ * DIMF];          // fp32 k pre-norm
__device__ __half g_xh[SEQ * DIMF];         // fp16 x
__device__ __half g_wqkv[DIMF * 3 * DIMF];  // fp16 fused [k][4608] qkv weights
__device__ __half g_who[DIMF * DIMF];       // fp16 wo
__device__ __half g_qh[NH * SEQ * HD];      // fp16 q, per-head, RoPE'd, pre-scaled (incl log2e)
__device__ __half g_kh[NH * LKV * HD];      // fp16 logical K, per-head contiguous
__device__ __half g_vh[NH * LKV * HD];      // fp16 logical V
__device__ __half g_oh[SEQ * DIMF];         // fp16 attention output

__device__ __forceinline__ unsigned pk2(float a, float b) {
    __half2 h = __floats2half2_rn(a, b);
    return *reinterpret_cast<unsigned*>(&h);
}
__device__ __forceinline__ unsigned ex2h2(unsigned x) {
    unsigned r; asm("ex2.approx.f16x2 %0, %1;" : "=r"(r) : "r"(x)); return r;
}
__device__ __forceinline__ uint4 cvt8(float4 a, float4 b) {
    uint4 u;
    u.x = pk2(a.x, a.y); u.y = pk2(a.z, a.w);
    u.z = pk2(b.x, b.y); u.w = pk2(b.z, b.w);
    return u;
}
__device__ __forceinline__ void mma16(float* d, const unsigned* a, const unsigned* b) {
    asm volatile(
        "mma.sync.aligned.m16n8k16.row.col.f32.f16.f16.f32 "
        "{%0,%1,%2,%3},{%4,%5,%6,%7},{%8,%9},{%0,%1,%2,%3};"
        : "+f"(d[0]), "+f"(d[1]), "+f"(d[2]), "+f"(d[3])
        : "r"(a[0]), "r"(a[1]), "r"(a[2]), "r"(a[3]), "r"(b[0]), "r"(b[1]));
}
__device__ __forceinline__ void ldm4(unsigned* r, const void* p) {
    unsigned a = (unsigned)__cvta_generic_to_shared(p);
    asm volatile("ldmatrix.sync.aligned.m8n8.x4.shared.b16 {%0,%1,%2,%3},[%4];"
                 : "=r"(r[0]), "=r"(r[1]), "=r"(r[2]), "=r"(r[3]) : "r"(a));
}
__device__ __forceinline__ void ldm4t(unsigned* r, const void* p) {
    unsigned a = (unsigned)__cvta_generic_to_shared(p);
    asm volatile("ldmatrix.sync.aligned.m8n8.x4.trans.shared.b16 {%0,%1,%2,%3},[%4];"
                 : "=r"(r[0]), "=r"(r[1]), "=r"(r[2]), "=r"(r[3]) : "r"(a));
}
__device__ __forceinline__ void ldm2t(unsigned* r, const void* p) {
    unsigned a = (unsigned)__cvta_generic_to_shared(p);
    asm volatile("ldmatrix.sync.aligned.m8n8.x2.trans.shared.b16 {%0,%1},[%2];"
                 : "=r"(r[0]), "=r"(r[1]) : "r"(a));
}
__device__ __forceinline__ void cpa16(void* dst, const void* src) {
    unsigned d = (unsigned)__cvta_generic_to_shared(dst);
    asm volatile("cp.async.cg.shared.global [%0], [%1], 16;" :: "r"(d), "l"(src));
}

// ---------------------------------------------------------------------------
// fp32 -> fp16 bulk convert (n % 8 == 0)
// ---------------------------------------------------------------------------
__global__ void f2h(const float* __restrict__ in, __half* __restrict__ out, int n) {
    int i = (blockIdx.x * blockDim.x + threadIdx.x) * 8;
    if (i < n) {
        float4 a = *(const float4*)(in + i);
        float4 b = *(const float4*)(in + i + 4);
        *(uint4*)(out + i) = cvt8(a, b);
    }
}

// ---------------------------------------------------------------------------
// fuse wq|wk|wv -> fp16 [k][4608]
// ---------------------------------------------------------------------------
__global__ void wfuse(const float* __restrict__ wq, const float* __restrict__ wk,
                      const float* __restrict__ wv, __half* __restrict__ out) {
    int idx = blockIdx.x * 256 + threadIdx.x;   // one uint4 (8 halfs) each
    if (idx >= DIMF * 576) return;              // 4608/8 = 576
    int k = idx / 576, n = (idx - k * 576) * 8;
    int sel = n / DIMF, nn = n - sel * DIMF;
    const float* src = (sel == 0 ? wq : sel == 1 ? wk : wv) + (size_t)k * DIMF + nn;
    float4 a = *(const float4*)src;
    float4 b = *(const float4*)(src + 4);
    *(uint4*)(out + (size_t)k * 4608 + n) = cvt8(a, b);
}

// ---------------------------------------------------------------------------
// cache rows -> per-head contiguous fp16 logical KV (flat-indexed)
// ---------------------------------------------------------------------------
__global__ __launch_bounds__(256) void cacheconv(
    const float* __restrict__ ck, const float* __restrict__ cv,
    __half* __restrict__ kh, __half* __restrict__ vh)
{
    int idx = blockIdx.x * 256 + threadIdx.x;
    if (idx >= 3120 * NH * 16) return;
    int d8 = (idx & 15) * 8;
    int jh = idx >> 4;
    int h = jh % NH;
    int j = jh / NH;
    int jj = j < 1560 ? j : j + 1560;
    size_t src = ((size_t)jj * NH + h) * HD + d8;
    size_t dst = ((size_t)h * LKV + j) * HD + d8;
    float4 a0 = *(const float4*)(ck + src);
    float4 a1 = *(const float4*)(ck + src + 4);
    *(uint4*)(kh + dst) = cvt8(a0, a1);
    float4 b0 = *(const float4*)(cv + src);
    float4 b1 = *(const float4*)(cv + src + 4);
    *(uint4*)(vh + dst) = cvt8(b0, b1);
}

// ---------------------------------------------------------------------------
// RMSNorm + RoPE; fp16 per-head outputs. q pre-scaled by log2e/sqrt(128).
// ---------------------------------------------------------------------------
__global__ __launch_bounds__(256) void rmsrope(
    const float* __restrict__ qbuf, const float* __restrict__ kbuf,
    const float* __restrict__ gq, const float* __restrict__ gk,
    const float* __restrict__ fre, const float* __restrict__ fim,
    __half* __restrict__ qh, __half* __restrict__ kh)
{
    const int t = blockIdx.x;
    const bool isq = blockIdx.y == 0;
    const float* row = (isq ? qbuf : kbuf) + (size_t)t * DIMF;
    const float* g = isq ? gq : gk;
    const int tid = threadIdx.x;

    float ss = 0.f;
#pragma unroll
    for (int u = 0; u < 6; u++) { float v = row[tid + u * 256]; ss += v * v; }
#pragma unroll
    for (int off = 16; off; off >>= 1) ss += __shfl_xor_sync(0xffffffffu, ss, off);
    __shared__ float red[8];
    if ((tid & 31) == 0) red[tid >> 5] = ss;
    __syncthreads();
    float tot = red[0] + red[1] + red[2] + red[3] + red[4] + red[5] + red[6] + red[7];
    float r = rsqrtf(tot * (1.f / 1536.f) + 1e-6f);
    const float sc = isq ? 0.08838834764831845f * 1.4426950408889634f : 1.0f;

    const int wi = t % 52;
    const int hi = t / 52;
#pragma unroll
    for (int u = 0; u < 3; u++) {
        int p = tid + u * 256;
        int hh = p >> 6, c = p & 63;
        int d0 = hh * 128 + 2 * c;
        int frow = (c < 22) ? 3 : (c < 43) ? hi : wi;
        float cr = fre[frow * 64 + c], ci = fim[frow * 64 + c];
        float v0 = row[d0] * r * g[d0];
        float v1 = row[d0 + 1] * r * g[d0 + 1];
        float y0 = (v0 * cr - v1 * ci) * sc;
        float y1 = (v0 * ci + v1 * cr) * sc;
        __half* dst = isq ? qh + ((size_t)hh * SEQ + t) * HD + 2 * c
                          : kh + ((size_t)hh * LKV + 3120 + t) * HD + 2 * c;
        *(__half2*)dst = __floats2half2_rn(y0, y1);
    }
}

// ---------------------------------------------------------------------------
// GEMM core (unchanged): BM=BN=128, BK=32, 128 thr, 3-stage cp.async.
// ---------------------------------------------------------------------------
#define GAS 40
#define GBS 136
#define ASTG (128 * GAS)
#define BSTG (32 * GBS)
#define GSTG (ASTG + BSTG)
#define NKT  48

template <int MODE, int LDW>
__global__ __launch_bounds__(128, 3) void gemm_core(
    const __half* __restrict__ A, const __half* __restrict__ W,
    const float* __restrict__ b0, const float* __restrict__ b1,
    const float* __restrict__ b2,
    float* __restrict__ o0, float* __restrict__ o1, __half* __restrict__ o2)
{
    extern __shared__ __half gsm[];
    const int bm = blockIdx.x * 128, bn = blockIdx.y * 128;
    const int tid = threadIdx.x, lane = tid & 31, warp = tid >> 5;
    const int wm = (warp >> 1) * 64, wn = (warp & 1) * 64;
    const int gi = lane >> 2, ti = lane & 3;

    float acc[4][8][4];
#pragma unroll
    for (int i = 0; i < 4; i++)
#pragma unroll
        for (int j = 0; j < 8; j++)
#pragma unroll
            for (int c = 0; c < 4; c++) acc[i][j][c] = 0.f;

    int arow = bm + tid; if (arow > SEQ - 1) arow = SEQ - 1;
    const __half* asrc = A + (size_t)arow * DIMF;
    const int brow = tid >> 2, bcol = (tid & 3) * 32;
    const __half* bsrc = W + (size_t)brow * LDW + bn + bcol;

#define GSTAGE(S, KT)                                                        \
    {                                                                        \
        __half* as_ = gsm + (S) * GSTG;                                      \
        __half* bs_ = as_ + ASTG;                                            \
        const __half* ap_ = asrc + (KT) * 32;                                \
        const __half* bp_ = bsrc + (size_t)(KT) * 32 * LDW;                  \
        _Pragma("unroll")                                                    \
        for (int u = 0; u < 4; u++) cpa16(as_ + tid * GAS + u * 8, ap_ + u * 8); \
        _Pragma("unroll")                                                    \
        for (int u = 0; u < 4; u++) cpa16(bs_ + brow * GBS + bcol + u * 8, bp_ + u * 8); \
        asm volatile("cp.async.commit_group;" ::: "memory");                 \
    }

    GSTAGE(0, 0)
    GSTAGE(1, 1)

    for (int kt = 0; kt < NKT; kt++) {
        if (kt < NKT - 1) asm volatile("cp.async.wait_group 1;" ::: "memory");
        else              asm volatile("cp.async.wait_group 0;" ::: "memory");
        __syncthreads();
        if (kt + 2 < NKT) { int s = (kt + 2) % 3; GSTAGE(s, kt + 2) }

        const __half* As = gsm + (kt % 3) * GSTG;
        const __half* Bs = As + ASTG;
#pragma unroll
        for (int ks = 0; ks < 2; ks++) {
            const int kk = ks * 16;
            unsigned a[4][4], b[4][4];
#pragma unroll
            for (int mt = 0; mt < 4; mt++)
                ldm4(a[mt], &As[(wm + 16 * mt + (lane & 15)) * GAS + kk + 8 * (lane >> 4)]);
#pragma unroll
            for (int ntp = 0; ntp < 4; ntp++)
                ldm4t(b[ntp], &Bs[(kk + (lane & 7) + 8 * ((lane >> 3) & 1)) * GBS
                                  + wn + 16 * ntp + 8 * (lane >> 4)]);
#pragma unroll
            for (int mt = 0; mt < 4; mt++)
#pragma unroll
                for (int ntp = 0; ntp < 4; ntp++) {
                    mma16(acc[mt][2 * ntp],     a[mt], &b[ntp][0]);
                    mma16(acc[mt][2 * ntp + 1], a[mt], &b[ntp][2]);
                }
        }
    }
#undef GSTAGE

    if (MODE == 0) {
#pragma unroll
        for (int mt = 0; mt < 4; mt++)
#pragma unroll
            for (int nt = 0; nt < 8; nt++) {
                int gr = bm + wm + 16 * mt + gi;
                int col = bn + wn + 8 * nt + 2 * ti;
                float2 bv = *(const float2*)&b0[col];
                if (gr < SEQ) {
                    float2 rr = { acc[mt][nt][0] + bv.x, acc[mt][nt][1] + bv.y };
                    *(float2*)(o0 + (size_t)gr * DIMF + col) = rr;
                }
                if (gr + 8 < SEQ) {
                    float2 rr = { acc[mt][nt][2] + bv.x, acc[mt][nt][3] + bv.y };
                    *(float2*)(o0 + (size_t)(gr + 8) * DIMF + col) = rr;
                }
            }
    } else {
        const int region = bn < DIMF ? 0 : bn < 2 * DIMF ? 1 : 2;
        const float* bp = region == 0 ? b0 + bn : region == 1 ? b1 + (bn - DIMF)
                                                              : b2 + (bn - 2 * DIMF);
#pragma unroll
        for (int mt = 0; mt < 4; mt++)
#pragma unroll
            for (int nt = 0; nt < 8; nt++) {
                int gr = bm + wm + 16 * mt + gi;
                int l = wn + 8 * nt + 2 * ti;
                float2 bv = *(const float2*)&bp[l];
                float v00 = acc[mt][nt][0] + bv.x, v01 = acc[mt][nt][1] + bv.y;
                float v10 = acc[mt][nt][2] + bv.x, v11 = acc[mt][nt][3] + bv.y;
                if (region == 0) {
                    int col = bn + l;
                    if (gr < SEQ)     *(float2*)(o0 + (size_t)gr * DIMF + col)       = make_float2(v00, v01);
                    if (gr + 8 < SEQ) *(float2*)(o0 + (size_t)(gr + 8) * DIMF + col) = make_float2(v10, v11);
                } else if (region == 1) {
                    int col = bn - DIMF + l;
                    if (gr < SEQ)     *(float2*)(o1 + (size_t)gr * DIMF + col)       = make_float2(v00, v01);
                    if (gr + 8 < SEQ) *(float2*)(o1 + (size_t)(gr + 8) * DIMF + col) = make_float2(v10, v11);
                } else {
                    int vcol = bn - 2 * DIMF + l;
                    int hh = vcol >> 7, d = vcol & 127;
                    if (gr < SEQ)
                        *(__half2*)(o2 + ((size_t)hh * LKV + 3120 + gr) * HD + d) =
                            __floats2half2_rn(v00, v01);
                    if (gr + 8 < SEQ)
                        *(__half2*)(o2 + ((size_t)hh * LKV + 3120 + gr + 8) * HD + d) =
                            __floats2half2_rn(v10, v11);
                }
            }
    }
}

// ---------------------------------------------------------------------------
// Flash attention, fp16. New this round: ex2.approx.f16x2 softmax (half the
// MUFU ops), l accumulated by the tensor core via a ones-column in V padding,
// __any_sync-guarded O rescale. q-tile 64, 128 thr, 3 blocks/SM.
// ---------------------------------------------------------------------------
#define KVS 136
#define TILEB (64 * KVS)
__global__ __launch_bounds__(128, 3) void attn_h(
    const __half* __restrict__ qh, const __half* __restrict__ kh,
    const __half* __restrict__ vh, __half* __restrict__ oh)
{
    extern __shared__ __half sm[];
    __half* Ks = sm;               // [2][64][KVS]
    __half* Vs = sm + 2 * TILEB;   // [2][64][KVS]; cols 128..135 = [1,0,...]

    const int h = blockIdx.y, q0 = blockIdx.x * 64;
    const int tid = threadIdx.x, lane = tid & 31, warp = tid >> 5;
    const int gi = lane >> 2, ti = lane & 3;

    const __half* kbase = kh + (size_t)h * LKV * HD;
    const __half* vbase = vh + (size_t)h * LKV * HD;

    const int srow = tid >> 1, scol = (tid & 1) * 64;

    // ones-column init: 128 threads cover 2 bufs x 64 rows
    {
        uint4 ones = { 0x00003C00u, 0u, 0u, 0u };   // [1.0h, 0 x7]
        *(uint4*)&Vs[tid * KVS + 128] = ones;
    }

    unsigned qf[8][4];
    {
        int r0 = q0 + warp * 16 + gi, r1 = r0 + 8;
        const __half* p0 = qh + ((size_t)h * SEQ + r0) * HD;
        const __half* p1 = qh + ((size_t)h * SEQ + r1) * HD;
        bool ok0 = r0 < SEQ, ok1 = r1 < SEQ;
#pragma unroll
        for (int kt = 0; kt < 8; kt++) {
            int c = 16 * kt + 2 * ti;
            qf[kt][0] = ok0 ? *(const unsigned*)(p0 + c)     : 0u;
            qf[kt][2] = ok0 ? *(const unsigned*)(p0 + c + 8) : 0u;
            qf[kt][1] = ok1 ? *(const unsigned*)(p1 + c)     : 0u;
            qf[kt][3] = ok1 ? *(const unsigned*)(p1 + c + 8) : 0u;
        }
    }

    float m0v = -1e30f, m1v = -1e30f;
    float o[16][4];
    float lacc[4] = { 0.f, 0.f, 0.f, 0.f };
#pragma unroll
    for (int i = 0; i < 16; i++)
#pragma unroll
        for (int c = 0; c < 4; c++) o[i][c] = 0.f;

    const int NT = (LKV + 63) / 64;   // 74

    {   // prologue: tile 0 -> buf 0
        const __half* kp = kbase + (size_t)srow * HD + scol;
        const __half* vp = vbase + (size_t)srow * HD + scol;
        __half* kd = Ks + srow * KVS + scol;
        __half* vd = Vs + srow * KVS + scol;
#pragma unroll
        for (int u = 0; u < 8; u++) {
            cpa16(kd + u * 8, kp + u * 8);
            cpa16(vd + u * 8, vp + u * 8);
        }
        asm volatile("cp.async.commit_group;" ::: "memory");
    }

    for (int t = 0; t < NT; t++) {
        const int buf = t & 1;
        if (t + 1 < NT) {
            int j = (t + 1) * 64 + srow;
            if (j > LKV - 1) j = LKV - 1;
            const int nb = (t + 1) & 1;
            const __half* kp = kbase + (size_t)j * HD + scol;
            const __half* vp = vbase + (size_t)j * HD + scol;
            __half* kd = Ks + nb * TILEB + srow * KVS + scol;
            __half* vd = Vs + nb * TILEB + srow * KVS + scol;
#pragma unroll
            for (int u = 0; u < 8; u++) {
                cpa16(kd + u * 8, kp + u * 8);
                cpa16(vd + u * 8, vp + u * 8);
            }
            asm volatile("cp.async.commit_group;" ::: "memory");
            asm volatile("cp.async.wait_group 1;" ::: "memory");
        } else {
            asm volatile("cp.async.wait_group 0;" ::: "memory");
        }
        __syncthreads();

        const __half* Kb = Ks + buf * TILEB;
        const __half* Vb = Vs + buf * TILEB;
        const int kv0 = t * 64;

        // --- S = Q K^T (logits in log2 domain via q pre-scale) ---
        float s[8][4];
#pragma unroll
        for (int nt = 0; nt < 8; nt++)
#pragma unroll
            for (int c = 0; c < 4; c++) s[nt][c] = 0.f;
#pragma unroll
        for (int kt = 0; kt < 8; kt++) {
            const int kk = 16 * kt;
#pragma unroll
            for (int ntp = 0; ntp < 4; ntp++) {
                unsigned b[4];
                ldm4(b, &Kb[(16 * ntp + (lane & 7) + 8 * ((lane >> 4) & 1)) * KVS
                            + kk + 8 * ((lane >> 3) & 1)]);
                mma16(s[2 * ntp],     qf[kt], &b[0]);
                mma16(s[2 * ntp + 1], qf[kt], &b[2]);
            }
        }

        if (kv0 + 64 > LKV) {
#pragma unroll
            for (int nt = 0; nt < 8; nt++) {
                int col = kv0 + 8 * nt + 2 * ti;
                if (col >= LKV)     { s[nt][0] = -1e30f; s[nt][2] = -1e30f; }
                if (col + 1 >= LKV) { s[nt][1] = -1e30f; s[nt][3] = -1e30f; }
            }
        }

        // --- online softmax: fp16x2 exp, conditional rescale ---
        float mx0 = -1e30f, mx1 = -1e30f;
#pragma unroll
        for (int nt = 0; nt < 8; nt++) {
            mx0 = fmaxf(mx0, fmaxf(s[nt][0], s[nt][1]));
            mx1 = fmaxf(mx1, fmaxf(s[nt][2], s[nt][3]));
        }
        mx0 = fmaxf(mx0, __shfl_xor_sync(0xffffffffu, mx0, 1));
        mx0 = fmaxf(mx0, __shfl_xor_sync(0xffffffffu, mx0, 2));
        mx1 = fmaxf(mx1, __shfl_xor_sync(0xffffffffu, mx1, 1));
        mx1 = fmaxf(mx1, __shfl_xor_sync(0xffffffffu, mx1, 2));
        float mn0 = fmaxf(m0v, mx0), mn1 = fmaxf(m1v, mx1);
        bool grew = (mn0 != m0v) || (mn1 != m1v);
        if (__any_sync(0xffffffffu, grew)) {
            float al0 = exp2f(m0v - mn0), al1 = exp2f(m1v - mn1);
#pragma unroll
            for (int nt = 0; nt < 16; nt++) {
                o[nt][0] *= al0; o[nt][1] *= al0;
                o[nt][2] *= al1; o[nt][3] *= al1;
            }
            lacc[0] *= al0; lacc[1] *= al0; lacc[2] *= al1; lacc[3] *= al1;
        }
        m0v = mn0; m1v = mn1;

        unsigned pf[4][4];
#pragma unroll
        for (int j = 0; j < 4; j++) {
            pf[j][0] = ex2h2(pk2(s[2 * j][0] - mn0,     s[2 * j][1] - mn0));
            pf[j][1] = ex2h2(pk2(s[2 * j][2] - mn1,     s[2 * j][3] - mn1));
            pf[j][2] = ex2h2(pk2(s[2 * j + 1][0] - mn0, s[2 * j + 1][1] - mn0));
            pf[j][3] = ex2h2(pk2(s[2 * j + 1][2] - mn1, s[2 * j + 1][3] - mn1));
        }

        // --- O += P V ; l += P * ones (extra n=8 mma into V padding) ---
#pragma unroll
        for (int j = 0; j < 4; j++) {
            const int vrow = (16 * j + (lane & 7) + 8 * ((lane >> 3) & 1)) * KVS;
#pragma unroll
            for (int ntp = 0; ntp < 8; ntp++) {
                unsigned b[4];
                ldm4t(b, &Vb[vrow + 16 * ntp + 8 * ((lane >> 4) & 1)]);
                mma16(o[2 * ntp],     pf[j], &b[0]);
                mma16(o[2 * ntp + 1], pf[j], &b[2]);
            }
            unsigned lb[2];
            ldm2t(lb, &Vb[vrow + 128]);
            mma16(lacc, pf[j], lb);
        }
        __syncthreads();
    }

    // epilogue: l lives in lane (gi*4), col 0 of the lacc fragment
    {
        float l0 = __shfl_sync(0xffffffffu, lacc[0], lane & 28);
        float l1 = __shfl_sync(0xffffffffu, lacc[2], lane & 28);
        int r0 = q0 + warp * 16 + gi, r1 = r0 + 8;
        float i0 = 1.f / l0, i1 = 1.f / l1;
#pragma unroll
        for (int nt = 0; nt < 16; nt++) {
            int c = h * HD + 8 * nt + 2 * ti;
            if (r0 < SEQ)
                *(__half2*)(oh + (size_t)r0 * DIMF + c) =
                    __floats2half2_rn(o[nt][0] * i0, o[nt][1] * i0);
            if (r1 < SEQ)
                *(__half2*)(oh + (size_t)r1 * DIMF + c) =
                    __floats2half2_rn(o[nt][2] * i1, o[nt][3] * i1);
        }
    }
}

// ---------------------------------------------------------------------------
extern "C" void kernel_launch(void* const* d_in, const int* in_sizes, int n_in,
                              void* d_out, int out_size)
{
    (void)in_sizes; (void)n_in; (void)out_size;
    const float* x   = (const float*)d_in[0];
    const float* ck  = (const float*)d_in[1];
    const float* cv  = (const float*)d_in[2];
    const float* fre = (const float*)d_in[3];
    const float* fim = (const float*)d_in[4];
    const float* wq  = (const float*)d_in[5];
    const float* bq  = (const float*)d_in[6];
    const float* wk  = (const float*)d_in[7];
    const float* bk  = (const float*)d_in[8];
    const float* wv  = (const float*)d_in[9];
    const float* bv  = (const float*)d_in[10];
    const float* wo  = (const float*)d_in[11];
    const float* bo  = (const float*)d_in[12];
    const float* gq  = (const float*)d_in[13];
    const float* gk  = (const float*)d_in[14];
    float* out = (float*)d_out;

    float *q, *k;
    __half *xh, *wqkv, *who, *qh, *kh, *vh, *oh;
    cudaGetSymbolAddress((void**)&q, g_q);
    cudaGetSymbolAddress((void**)&k, g_k);
    cudaGetSymbolAddress((void**)&xh, g_xh);
    cudaGetSymbolAddress((void**)&wqkv, g_wqkv);
    cudaGetSymbolAddress((void**)&who, g_who);
    cudaGetSymbolAddress((void**)&qh, g_qh);
    cudaGetSymbolAddress((void**)&kh, g_kh);
    cudaGetSymbolAddress((void**)&vh, g_vh);
    cudaGetSymbolAddress((void**)&oh, g_oh);

    const int gemm_smem = 3 * GSTG * (int)sizeof(__half);   // 56832
    const int attn_smem = 4 * TILEB * (int)sizeof(__half);  // 69632
    cudaFuncSetAttribute((const void*)gemm_core<1, 4608>,
                         cudaFuncAttributeMaxDynamicSharedMemorySize, gemm_smem);
    cudaFuncSetAttribute((const void*)gemm_core<0, 1536>,
                         cudaFuncAttributeMaxDynamicSharedMemorySize, gemm_smem);
    cudaFuncSetAttribute((const void*)attn_h,
                         cudaFuncAttributeMaxDynamicSharedMemorySize, attn_smem);

    const int NW = DIMF * DIMF;
    const int NX = SEQ * DIMF;
    // order chosen so attn_h is the 6th launch (ncu -s 5 -c 1 captures it)
    f2h<<<(NX / 8 + 255) / 256, 256>>>(x, xh, NX);                     // 1
    wfuse<<<(DIMF * 576 + 255) / 256, 256>>>(wq, wk, wv, wqkv);        // 2
    cacheconv<<<(3120 * NH * 16 + 255) / 256, 256>>>(ck, cv, kh, vh);  // 3
    gemm_core<1, 4608><<<dim3(13, 36), 128, gemm_smem>>>(
        xh, wqkv, bq, bk, bv, q, k, vh);                               // 4
    rmsrope<<<dim3(SEQ, 2), 256>>>(q, k, gq, gk, fre, fim, qh, kh);    // 5
    attn_h<<<dim3(25, NH), 128, attn_smem>>>(qh, kh, vh, oh);          // 6
    f2h<<<(NW / 8 + 255) / 256, 256>>>(wo, who, NW);                   // 7
    gemm_core<0, 1536><<<dim3(13, 12), 128, gemm_smem>>>(
        oh, who, bo, nullptr, nullptr, out, nullptr, nullptr);         // 8
}

// round 13
// speedup vs baseline: 2.3529x; 1.5541x over previous
#include <cuda_runtime.h>
#include <cuda_fp16.h>

#define DIMF 1536
#define SEQ  1560
#define LKV  4680
#define NH   12
#define HD   128

// ---------------- device-global scratch (allocation-free) ----------------
__device__ float  g_q[SEQ * DIMF];            // fp32 q pre-norm
__device__ float  g_k[SEQ * DIMF];            // fp32 k pre-norm
__device__ __half g_xh[SEQ * DIMF];           // fp16 x
__device__ __half g_wt[3 * DIMF * DIMF];      // fp16 W^T qkv: [n 4608][k 1536]
__device__ __half g_wot[DIMF * DIMF];         // fp16 Wo^T: [n][k]
__device__ __half g_qh[NH * SEQ * HD];        // fp16 q per-head (RoPE'd, prescaled)
__device__ __half g_kh[NH * LKV * HD];        // fp16 logical K per-head
__device__ __half g_vh[NH * LKV * HD];        // fp16 logical V per-head
__device__ __half g_oh[SEQ * DIMF];           // fp16 attention output

__device__ __forceinline__ unsigned pk2(float a, float b) {
    __half2 h = __floats2half2_rn(a, b);
    return *reinterpret_cast<unsigned*>(&h);
}
__device__ __forceinline__ unsigned ex2h2(unsigned x) {
    unsigned r; asm("ex2.approx.f16x2 %0, %1;" : "=r"(r) : "r"(x)); return r;
}
__device__ __forceinline__ uint4 cvt8(float4 a, float4 b) {
    uint4 u;
    u.x = pk2(a.x, a.y); u.y = pk2(a.z, a.w);
    u.z = pk2(b.x, b.y); u.w = pk2(b.z, b.w);
    return u;
}
__device__ __forceinline__ void mma16(float* d, const unsigned* a, const unsigned* b) {
    asm volatile(
        "mma.sync.aligned.m16n8k16.row.col.f32.f16.f16.f32 "
        "{%0,%1,%2,%3},{%4,%5,%6,%7},{%8,%9},{%0,%1,%2,%3};"
        : "+f"(d[0]), "+f"(d[1]), "+f"(d[2]), "+f"(d[3])
        : "r"(a[0]), "r"(a[1]), "r"(a[2]), "r"(a[3]), "r"(b[0]), "r"(b[1]));
}
__device__ __forceinline__ void ldm4(unsigned* r, const void* p) {
    unsigned a = (unsigned)__cvta_generic_to_shared(p);
    asm volatile("ldmatrix.sync.aligned.m8n8.x4.shared.b16 {%0,%1,%2,%3},[%4];"
                 : "=r"(r[0]), "=r"(r[1]), "=r"(r[2]), "=r"(r[3]) : "r"(a));
}
__device__ __forceinline__ void ldm4t(unsigned* r, const void* p) {
    unsigned a = (unsigned)__cvta_generic_to_shared(p);
    asm volatile("ldmatrix.sync.aligned.m8n8.x4.trans.shared.b16 {%0,%1,%2,%3},[%4];"
                 : "=r"(r[0]), "=r"(r[1]), "=r"(r[2]), "=r"(r[3]) : "r"(a));
}
__device__ __forceinline__ void ldm2t(unsigned* r, const void* p) {
    unsigned a = (unsigned)__cvta_generic_to_shared(p);
    asm volatile("ldmatrix.sync.aligned.m8n8.x2.trans.shared.b16 {%0,%1},[%2];"
                 : "=r"(r[0]), "=r"(r[1]) : "r"(a));
}
__device__ __forceinline__ void cpa16(void* dst, const void* src) {
    unsigned d = (unsigned)__cvta_generic_to_shared(dst);
    asm volatile("cp.async.cg.shared.global [%0], [%1], 16;" :: "r"(d), "l"(src));
}

// ---------------------------------------------------------------------------
// fp32 -> fp16 bulk convert
// ---------------------------------------------------------------------------
__global__ void f2h(const float* __restrict__ in, __half* __restrict__ out, int n) {
    int i = (blockIdx.x * blockDim.x + threadIdx.x) * 8;
    if (i < n) {
        float4 a = *(const float4*)(in + i);
        float4 b = *(const float4*)(in + i + 4);
        *(uint4*)(out + i) = cvt8(a, b);
    }
}

// ---------------------------------------------------------------------------
// W [k][n] fp32 -> W^T [n][k] fp16, tiled transpose (region = bn/1536 picks src)
// ---------------------------------------------------------------------------
__global__ __launch_bounds__(256) void wtrans(
    const float* __restrict__ s0, const float* __restrict__ s1,
    const float* __restrict__ s2, __half* __restrict__ wT)
{
    __shared__ float t[32][33];
    int bn = blockIdx.x * 32, bk = blockIdx.y * 32;
    int region = bn / DIMF;
    const float* src = region == 0 ? s0 : region == 1 ? s1 : s2;
    int ln = bn - region * DIMF;
    int tx = threadIdx.x, ty = threadIdx.y;
#pragma unroll
    for (int i = ty; i < 32; i += 8)
        t[i][tx] = src[(size_t)(bk + i) * DIMF + ln + tx];
    __syncthreads();
#pragma unroll
    for (int i = ty; i < 32; i += 8)
        wT[(size_t)(bn + i) * DIMF + bk + tx] = __float2half(t[tx][i]);
}

// ---------------------------------------------------------------------------
// cache rows -> per-head contiguous fp16 logical KV (proven round-10 version)
// ---------------------------------------------------------------------------
__global__ __launch_bounds__(256) void cacheconv(
    const float* __restrict__ ck, const float* __restrict__ cv,
    __half* __restrict__ kh, __half* __restrict__ vh)
{
    int idx = blockIdx.x * 256 + threadIdx.x;
    if (idx >= 3120 * NH * 16) return;
    int d8 = (idx & 15) * 8;
    int jh = idx >> 4;
    int h = jh % NH;
    int j = jh / NH;
    int jj = j < 1560 ? j : j + 1560;
    size_t src = ((size_t)jj * NH + h) * HD + d8;
    size_t dst = ((size_t)h * LKV + j) * HD + d8;
    float4 a0 = *(const float4*)(ck + src);
    float4 a1 = *(const float4*)(ck + src + 4);
    *(uint4*)(kh + dst) = cvt8(a0, a1);
    float4 b0 = *(const float4*)(cv + src);
    float4 b1 = *(const float4*)(cv + src + 4);
    *(uint4*)(vh + dst) = cvt8(b0, b1);
}

// ---------------------------------------------------------------------------
// RMSNorm + RoPE (unchanged)
// ---------------------------------------------------------------------------
__global__ __launch_bounds__(256) void rmsrope(
    const float* __restrict__ qbuf, const float* __restrict__ kbuf,
    const float* __restrict__ gq, const float* __restrict__ gk,
    const float* __restrict__ fre, const float* __restrict__ fim,
    __half* __restrict__ qh, __half* __restrict__ kh)
{
    const int t = blockIdx.x;
    const bool isq = blockIdx.y == 0;
    const float* row = (isq ? qbuf : kbuf) + (size_t)t * DIMF;
    const float* g = isq ? gq : gk;
    const int tid = threadIdx.x;

    float ss = 0.f;
#pragma unroll
    for (int u = 0; u < 6; u++) { float v = row[tid + u * 256]; ss += v * v; }
#pragma unroll
    for (int off = 16; off; off >>= 1) ss += __shfl_xor_sync(0xffffffffu, ss, off);
    __shared__ float red[8];
    if ((tid & 31) == 0) red[tid >> 5] = ss;
    __syncthreads();
    float tot = red[0] + red[1] + red[2] + red[3] + red[4] + red[5] + red[6] + red[7];
    float r = rsqrtf(tot * (1.f / 1536.f) + 1e-6f);
    const float sc = isq ? 0.08838834764831845f * 1.4426950408889634f : 1.0f;

    const int wi = t % 52;
    const int hi = t / 52;
#pragma unroll
    for (int u = 0; u < 3; u++) {
        int p = tid + u * 256;
        int hh = p >> 6, c = p & 63;
        int d0 = hh * 128 + 2 * c;
        int frow = (c < 22) ? 3 : (c < 43) ? hi : wi;
        float cr = fre[frow * 64 + c], ci = fim[frow * 64 + c];
        float v0 = row[d0] * r * g[d0];
        float v1 = row[d0 + 1] * r * g[d0 + 1];
        float y0 = (v0 * cr - v1 * ci) * sc;
        float y1 = (v0 * ci + v1 * cr) * sc;
        __half* dst = isq ? qh + ((size_t)hh * SEQ + t) * HD + 2 * c
                          : kh + ((size_t)hh * LKV + 3120 + t) * HD + 2 * c;
        *(__half2*)dst = __floats2half2_rn(y0, y1);
    }
}

// ---------------------------------------------------------------------------
// GEMM (mma.sync): BM=BN=128, BK=64, 128 threads, warp tile 64x64.
// A [m][k] fp16, W^T [n][k] fp16 -- both staged with COALESCED cp.async
// (consecutive lanes = consecutive 16B of one row: 4 wavefronts/instr).
// Both operands feed plain ldm4. 2-stage pipeline, 3 blocks/SM.
// MODE 1: fused QKV; MODE 0: O-proj.
// ---------------------------------------------------------------------------
#define GAS 72                     // halfs per staged row (64 + 8 pad)
#define ASTGB (128 * GAS * 2)      // bytes of A region per stage
#define STAGEB (2 * ASTGB)         // A + B
#define NKT 24                     // 1536 / 64

template <int MODE>
__global__ __launch_bounds__(128, 3) void gemm_h(
    const __half* __restrict__ A, const __half* __restrict__ WT,
    const float* __restrict__ b0, const float* __restrict__ b1,
    const float* __restrict__ b2,
    float* __restrict__ o0, float* __restrict__ o1, __half* __restrict__ o2)
{
    extern __shared__ char gsm[];
    const int bm = blockIdx.x * 128, bn = blockIdx.y * 128;
    const int tid = threadIdx.x, lane = tid & 31, warp = tid >> 5;
    const int wm = (warp >> 1) * 64, wn = (warp & 1) * 64;
    const int gi = lane >> 2, ti = lane & 3;

    float acc[4][8][4];
#pragma unroll
    for (int i = 0; i < 4; i++)
#pragma unroll
        for (int j = 0; j < 8; j++)
#pragma unroll
            for (int c = 0; c < 4; c++) acc[i][j][c] = 0.f;

    const char* Ab = (const char*)A;
    const char* Bb = (const char*)WT;

#define GSTAGE(S, CH)                                                         \
    {                                                                         \
        char* sb_ = gsm + (S) * STAGEB;                                       \
        _Pragma("unroll")                                                     \
        for (int u = 0; u < 8; u++) {                                         \
            int off = u * 2048 + tid * 16;                                    \
            int r = off >> 7, cb = off & 127;                                 \
            int gr = bm + r; if (gr > SEQ - 1) gr = SEQ - 1;                  \
            cpa16(sb_ + r * 144 + cb, Ab + (size_t)gr * 3072 + (CH) * 128 + cb); \
        }                                                                     \
        _Pragma("unroll")                                                     \
        for (int u = 0; u < 8; u++) {                                         \
            int off = u * 2048 + tid * 16;                                    \
            int r = off >> 7, cb = off & 127;                                 \
            cpa16(sb_ + ASTGB + r * 144 + cb,                                 \
                  Bb + (size_t)(bn + r) * 3072 + (CH) * 128 + cb);            \
        }                                                                     \
        asm volatile("cp.async.commit_group;" ::: "memory");                  \
    }

    GSTAGE(0, 0)
    GSTAGE(1, 1)

    for (int ch = 0; ch < NKT; ch++) {
        const int S = ch & 1;
        if (ch == NKT - 1) asm volatile("cp.async.wait_group 0;" ::: "memory");
        else               asm volatile("cp.async.wait_group 1;" ::: "memory");
        __syncthreads();

        const __half* As = (const __half*)(gsm + S * STAGEB);
        const __half* Bs = (const __half*)(gsm + S * STAGEB + ASTGB);
#pragma unroll
        for (int ks = 0; ks < 4; ks++) {
            const int kk = ks * 16;
            unsigned a[4][4], b[4][4];
#pragma unroll
            for (int mt = 0; mt < 4; mt++)
                ldm4(a[mt], &As[(wm + 16 * mt + (lane & 15)) * GAS
                                + kk + 8 * (lane >> 4)]);
#pragma unroll
            for (int ntp = 0; ntp < 4; ntp++)
                ldm4(b[ntp], &Bs[(wn + 16 * ntp + (lane & 7) + 8 * ((lane >> 4) & 1)) * GAS
                                 + kk + 8 * ((lane >> 3) & 1)]);
#pragma unroll
            for (int mt = 0; mt < 4; mt++)
#pragma unroll
                for (int ntp = 0; ntp < 4; ntp++) {
                    mma16(acc[mt][2 * ntp],     a[mt], &b[ntp][0]);
                    mma16(acc[mt][2 * ntp + 1], a[mt], &b[ntp][2]);
                }
        }
        __syncthreads();
        if (ch + 2 < NKT) GSTAGE(S, ch + 2)
    }
#undef GSTAGE

    // ---- epilogue (identical structure to round 11, proven) ----
    if (MODE == 0) {
#pragma unroll
        for (int mt = 0; mt < 4; mt++)
#pragma unroll
            for (int nt = 0; nt < 8; nt++) {
                int gr = bm + wm + 16 * mt + gi;
                int col = bn + wn + 8 * nt + 2 * ti;
                float2 bv = *(const float2*)&b0[col];
                if (gr < SEQ) {
                    float2 rr = { acc[mt][nt][0] + bv.x, acc[mt][nt][1] + bv.y };
                    *(float2*)(o0 + (size_t)gr * DIMF + col) = rr;
                }
                if (gr + 8 < SEQ) {
                    float2 rr = { acc[mt][nt][2] + bv.x, acc[mt][nt][3] + bv.y };
                    *(float2*)(o0 + (size_t)(gr + 8) * DIMF + col) = rr;
                }
            }
    } else {
        const int region = bn < DIMF ? 0 : bn < 2 * DIMF ? 1 : 2;
        const float* bp = region == 0 ? b0 + bn : region == 1 ? b1 + (bn - DIMF)
                                                              : b2 + (bn - 2 * DIMF);
#pragma unroll
        for (int mt = 0; mt < 4; mt++)
#pragma unroll
            for (int nt = 0; nt < 8; nt++) {
                int gr = bm + wm + 16 * mt + gi;
                int l = wn + 8 * nt + 2 * ti;
                float2 bv = *(const float2*)&bp[l];
                float v00 = acc[mt][nt][0] + bv.x, v01 = acc[mt][nt][1] + bv.y;
                float v10 = acc[mt][nt][2] + bv.x, v11 = acc[mt][nt][3] + bv.y;
                if (region == 0) {
                    int col = bn + l;
                    if (gr < SEQ)     *(float2*)(o0 + (size_t)gr * DIMF + col)       = make_float2(v00, v01);
                    if (gr + 8 < SEQ) *(float2*)(o0 + (size_t)(gr + 8) * DIMF + col) = make_float2(v10, v11);
                } else if (region == 1) {
                    int col = bn - DIMF + l;
                    if (gr < SEQ)     *(float2*)(o1 + (size_t)gr * DIMF + col)       = make_float2(v00, v01);
                    if (gr + 8 < SEQ) *(float2*)(o1 + (size_t)(gr + 8) * DIMF + col) = make_float2(v10, v11);
                } else {
                    int vcol = bn - 2 * DIMF + l;
                    int hh = vcol >> 7, d = vcol & 127;
                    if (gr < SEQ)
                        *(__half2*)(o2 + ((size_t)hh * LKV + 3120 + gr) * HD + d) =
                            __floats2half2_rn(v00, v01);
                    if (gr + 8 < SEQ)
                        *(__half2*)(o2 + ((size_t)hh * LKV + 3120 + gr + 8) * HD + d) =
                            __floats2half2_rn(v10, v11);
                }
            }
    }
}

// ---------------------------------------------------------------------------
// Flash attention (round-11 mainloop; staging remapped to coalesced cp.async:
// 16 lanes cover one 256B KV row -> 4 wavefronts/instr instead of 16).
// ---------------------------------------------------------------------------
#define KVS 136
#define TILEB (64 * KVS)
__global__ __launch_bounds__(128, 3) void attn_h(
    const __half* __restrict__ qh, const __half* __restrict__ kh,
    const __half* __restrict__ vh, __half* __restrict__ oh)
{
    extern __shared__ __half sm[];
    __half* Ks = sm;
    __half* Vs = sm + 2 * TILEB;

    const int h = blockIdx.y, q0 = blockIdx.x * 64;
    const int tid = threadIdx.x, lane = tid & 31, warp = tid >> 5;
    const int gi = lane >> 2, ti = lane & 3;

    const char* kbase = (const char*)(kh + (size_t)h * LKV * HD);
    const char* vbase = (const char*)(vh + (size_t)h * LKV * HD);

    {
        uint4 ones = { 0x00003C00u, 0u, 0u, 0u };
        *(uint4*)&Vs[tid * KVS + 128] = ones;
    }

    unsigned qf[8][4];
    {
        int r0 = q0 + warp * 16 + gi, r1 = r0 + 8;
        const __half* p0 = qh + ((size_t)h * SEQ + r0) * HD;
        const __half* p1 = qh + ((size_t)h * SEQ + r1) * HD;
        bool ok0 = r0 < SEQ, ok1 = r1 < SEQ;
#pragma unroll
        for (int kt = 0; kt < 8; kt++) {
            int c = 16 * kt + 2 * ti;
            qf[kt][0] = ok0 ? *(const unsigned*)(p0 + c)     : 0u;
            qf[kt][2] = ok0 ? *(const unsigned*)(p0 + c + 8) : 0u;
            qf[kt][1] = ok1 ? *(const unsigned*)(p1 + c)     : 0u;
            qf[kt][3] = ok1 ? *(const unsigned*)(p1 + c + 8) : 0u;
        }
    }

    float m0v = -1e30f, m1v = -1e30f;
    float o[16][4];
    float lacc[4] = { 0.f, 0.f, 0.f, 0.f };
#pragma unroll
    for (int i = 0; i < 16; i++)
#pragma unroll
        for (int c = 0; c < 4; c++) o[i][c] = 0.f;

    const int NT = (LKV + 63) / 64;

// coalesced KV staging of tile starting at kv row JBASE into buffers kd/vd
#define KVSTAGE(kd, vd, JBASE)                                                \
    {                                                                         \
        _Pragma("unroll")                                                     \
        for (int u = 0; u < 8; u++) {                                         \
            int off = u * 2048 + tid * 16;                                    \
            int r = off >> 8, cb = off & 255;                                 \
            int j = (JBASE) + r; if (j > LKV - 1) j = LKV - 1;                \
            cpa16((char*)(kd) + r * 272 + cb, kbase + (size_t)j * 256 + cb);  \
            cpa16((char*)(vd) + r * 272 + cb, vbase + (size_t)j * 256 + cb);  \
        }                                                                     \
        asm volatile("cp.async.commit_group;" ::: "memory");                  \
    }

    KVSTAGE(Ks, Vs, 0)

    for (int t = 0; t < NT; t++) {
        const int buf = t & 1;
        if (t + 1 < NT) {
            const int nb = (t + 1) & 1;
            KVSTAGE(Ks + nb * TILEB, Vs + nb * TILEB, (t + 1) * 64)
            asm volatile("cp.async.wait_group 1;" ::: "memory");
        } else {
            asm volatile("cp.async.wait_group 0;" ::: "memory");
        }
        __syncthreads();

        const __half* Kb = Ks + buf * TILEB;
        const __half* Vb = Vs + buf * TILEB;
        const int kv0 = t * 64;

        float s[8][4];
#pragma unroll
        for (int nt = 0; nt < 8; nt++)
#pragma unroll
            for (int c = 0; c < 4; c++) s[nt][c] = 0.f;
#pragma unroll
        for (int kt = 0; kt < 8; kt++) {
            const int kk = 16 * kt;
#pragma unroll
            for (int ntp = 0; ntp < 4; ntp++) {
                unsigned b[4];
                ldm4(b, &Kb[(16 * ntp + (lane & 7) + 8 * ((lane >> 4) & 1)) * KVS
                            + kk + 8 * ((lane >> 3) & 1)]);
                mma16(s[2 * ntp],     qf[kt], &b[0]);
                mma16(s[2 * ntp + 1], qf[kt], &b[2]);
            }
        }

        if (kv0 + 64 > LKV) {
#pragma unroll
            for (int nt = 0; nt < 8; nt++) {
                int col = kv0 + 8 * nt + 2 * ti;
                if (col >= LKV)     { s[nt][0] = -1e30f; s[nt][2] = -1e30f; }
                if (col + 1 >= LKV) { s[nt][1] = -1e30f; s[nt][3] = -1e30f; }
            }
        }

        float mx0 = -1e30f, mx1 = -1e30f;
#pragma unroll
        for (int nt = 0; nt < 8; nt++) {
            mx0 = fmaxf(mx0, fmaxf(s[nt][0], s[nt][1]));
            mx1 = fmaxf(mx1, fmaxf(s[nt][2], s[nt][3]));
        }
        mx0 = fmaxf(mx0, __shfl_xor_sync(0xffffffffu, mx0, 1));
        mx0 = fmaxf(mx0, __shfl_xor_sync(0xffffffffu, mx0, 2));
        mx1 = fmaxf(mx1, __shfl_xor_sync(0xffffffffu, mx1, 1));
        mx1 = fmaxf(mx1, __shfl_xor_sync(0xffffffffu, mx1, 2));
        float mn0 = fmaxf(m0v, mx0), mn1 = fmaxf(m1v, mx1);
        bool grew = (mn0 != m0v) || (mn1 != m1v);
        if (__any_sync(0xffffffffu, grew)) {
            float al0 = exp2f(m0v - mn0), al1 = exp2f(m1v - mn1);
#pragma unroll
            for (int nt = 0; nt < 16; nt++) {
                o[nt][0] *= al0; o[nt][1] *= al0;
                o[nt][2] *= al1; o[nt][3] *= al1;
            }
            lacc[0] *= al0; lacc[1] *= al0; lacc[2] *= al1; lacc[3] *= al1;
        }
        m0v = mn0; m1v = mn1;

        unsigned pf[4][4];
#pragma unroll
        for (int j = 0; j < 4; j++) {
            pf[j][0] = ex2h2(pk2(s[2 * j][0] - mn0,     s[2 * j][1] - mn0));
            pf[j][1] = ex2h2(pk2(s[2 * j][2] - mn1,     s[2 * j][3] - mn1));
            pf[j][2] = ex2h2(pk2(s[2 * j + 1][0] - mn0, s[2 * j + 1][1] - mn0));
            pf[j][3] = ex2h2(pk2(s[2 * j + 1][2] - mn1, s[2 * j + 1][3] - mn1));
        }

#pragma unroll
        for (int j = 0; j < 4; j++) {
            const int vrow = (16 * j + (lane & 7) + 8 * ((lane >> 3) & 1)) * KVS;
#pragma unroll
            for (int ntp = 0; ntp < 8; ntp++) {
                unsigned b[4];
                ldm4t(b, &Vb[vrow + 16 * ntp + 8 * ((lane >> 4) & 1)]);
                mma16(o[2 * ntp],     pf[j], &b[0]);
                mma16(o[2 * ntp + 1], pf[j], &b[2]);
            }
            unsigned lb[2];
            ldm2t(lb, &Vb[vrow + 128]);
            mma16(lacc, pf[j], lb);
        }
        __syncthreads();
    }
#undef KVSTAGE

    {
        float l0 = __shfl_sync(0xffffffffu, lacc[0], lane & 28);
        float l1 = __shfl_sync(0xffffffffu, lacc[2], lane & 28);
        int r0 = q0 + warp * 16 + gi, r1 = r0 + 8;
        float i0 = 1.f / l0, i1 = 1.f / l1;
#pragma unroll
        for (int nt = 0; nt < 16; nt++) {
            int c = h * HD + 8 * nt + 2 * ti;
            if (r0 < SEQ)
                *(__half2*)(oh + (size_t)r0 * DIMF + c) =
                    __floats2half2_rn(o[nt][0] * i0, o[nt][1] * i0);
            if (r1 < SEQ)
                *(__half2*)(oh + (size_t)r1 * DIMF + c) =
                    __floats2half2_rn(o[nt][2] * i1, o[nt][3] * i1);
        }
    }
}

// ---------------------------------------------------------------------------
extern "C" void kernel_launch(void* const* d_in, const int* in_sizes, int n_in,
                              void* d_out, int out_size)
{
    (void)in_sizes; (void)n_in; (void)out_size;
    const float* x   = (const float*)d_in[0];
    const float* ck  = (const float*)d_in[1];
    const float* cv  = (const float*)d_in[2];
    const float* fre = (const float*)d_in[3];
    const float* fim = (const float*)d_in[4];
    const float* wq  = (const float*)d_in[5];
    const float* bq  = (const float*)d_in[6];
    const float* wk  = (const float*)d_in[7];
    const float* bk  = (const float*)d_in[8];
    const float* wv  = (const float*)d_in[9];
    const float* bv  = (const float*)d_in[10];
    const float* wo  = (const float*)d_in[11];
    const float* bo  = (const float*)d_in[12];
    const float* gq  = (const float*)d_in[13];
    const float* gk  = (const float*)d_in[14];
    float* out = (float*)d_out;

    float *q, *k;
    __half *xh, *wt, *wot, *qh, *kh, *vh, *oh;
    cudaGetSymbolAddress((void**)&q, g_q);
    cudaGetSymbolAddress((void**)&k, g_k);
    cudaGetSymbolAddress((void**)&xh, g_xh);
    cudaGetSymbolAddress((void**)&wt, g_wt);
    cudaGetSymbolAddress((void**)&wot, g_wot);
    cudaGetSymbolAddress((void**)&qh, g_qh);
    cudaGetSymbolAddress((void**)&kh, g_kh);
    cudaGetSymbolAddress((void**)&vh, g_vh);
    cudaGetSymbolAddress((void**)&oh, g_oh);

    const int gemm_smem = 2 * STAGEB;                       // 73728
    const int attn_smem = 4 * TILEB * (int)sizeof(__half);  // 69632
    cudaFuncSetAttribute((const void*)gemm_h<1>,
                         cudaFuncAttributeMaxDynamicSharedMemorySize, gemm_smem);
    cudaFuncSetAttribute((const void*)gemm_h<0>,
                         cudaFuncAttributeMaxDynamicSharedMemorySize, gemm_smem);
    cudaFuncSetAttribute((const void*)attn_h,
                         cudaFuncAttributeMaxDynamicSharedMemorySize, attn_smem);

    const int NX = SEQ * DIMF;
    // order: attn_h is launch #6 (ncu -s 5 -c 1 captures it)
    f2h<<<(NX / 8 + 255) / 256, 256>>>(x, xh, NX);                        // 1
    wtrans<<<dim3(144, 48), dim3(32, 8)>>>(wq, wk, wv, wt);               // 2
    cacheconv<<<(3120 * NH * 16 + 255) / 256, 256>>>(ck, cv, kh, vh);     // 3
    gemm_h<1><<<dim3(13, 36), 128, gemm_smem>>>(                          // 4
        xh, wt, bq, bk, bv, q, k, vh);
    rmsrope<<<dim3(SEQ, 2), 256>>>(q, k, gq, gk, fre, fim, qh, kh);       // 5
    attn_h<<<dim3(25, NH), 128, attn_smem>>>(qh, kh, vh, oh);             // 6
    wtrans<<<dim3(48, 48), dim3(32, 8)>>>(wo, wo, wo, wot);               // 7
    gemm_h<0><<<dim3(13, 12), 128, gemm_smem>>>(                          // 8
        oh, wot, bo, nullptr, nullptr, out, nullptr, nullptr);
}